// round 1
// baseline (speedup 1.0000x reference)
#include <cuda_runtime.h>
#include <math.h>
#include <stdint.h>

#define BQ   8
#define CC   256
#define HH   128
#define WWD  128
#define GG   16
#define NWIN 512     // 8 * 8 * 8 windows
#define NT   256     // tokens per window (16*16)
#define C8   32
#define FF   1024

// ---------------- device scratch (no dynamic allocation allowed) -------------
__device__ __align__(128) float g_q[(size_t)NWIN * NT * C8];   // [w][m][o]
__device__ __align__(128) float g_k[(size_t)NWIN * NT * C8];   // [w][n][o]
__device__ __align__(128) float g_e[(size_t)NWIN * NT * NT];   // [w][n][m] = exp(l[m][n]-max[m])
__device__ __align__(128) float g_z[(size_t)NWIN * NT];        // [w][m] row sums
__device__ __align__(128) float g_t[(size_t)NWIN * NT * NT];   // [w][ch][m]
__device__ __align__(128) float g_xa[(size_t)BQ * CC * HH * WWD];

// ------------------------------------------------------------------
// Kernel 1: q = Wq @ xw, k = Wk @ xw  per window (block = window)
// ------------------------------------------------------------------
__global__ void __launch_bounds__(256) qk_kernel(const float* __restrict__ x,
                                                 const float* __restrict__ Wq,
                                                 const float* __restrict__ Wk)
{
    extern __shared__ float s[];
    float* sq = s;              // [32][256]
    float* sk = s + C8 * CC;    // [32][256]
    int tid = threadIdx.x;
    for (int i = tid; i < C8 * CC; i += 256) { sq[i] = Wq[i]; sk[i] = Wk[i]; }
    __syncthreads();

    int w = blockIdx.x;
    int b = w >> 6, r = w & 63, ih = r >> 3, iw = r & 7;
    int n = tid, gy = n >> 4, gx = n & 15;
    const float* xp = x + (size_t)b * CC * HH * WWD + (ih * GG + gy) * WWD + iw * GG + gx;

    float qa[C8], ka[C8];
#pragma unroll
    for (int o = 0; o < C8; o++) { qa[o] = 0.f; ka[o] = 0.f; }

    for (int c = 0; c < CC; c += 4) {
        float v0 = xp[(size_t)(c + 0) * HH * WWD];
        float v1 = xp[(size_t)(c + 1) * HH * WWD];
        float v2 = xp[(size_t)(c + 2) * HH * WWD];
        float v3 = xp[(size_t)(c + 3) * HH * WWD];
#pragma unroll
        for (int o = 0; o < C8; o++) {
            float4 a = *(const float4*)&sq[o * CC + c];
            qa[o] = fmaf(a.x, v0, fmaf(a.y, v1, fmaf(a.z, v2, fmaf(a.w, v3, qa[o]))));
            float4 bb = *(const float4*)&sk[o * CC + c];
            ka[o] = fmaf(bb.x, v0, fmaf(bb.y, v1, fmaf(bb.z, v2, fmaf(bb.w, v3, ka[o]))));
        }
    }
    float* qdst = g_q + (size_t)w * NT * C8 + n * C8;
    float* kdst = g_k + (size_t)w * NT * C8 + n * C8;
#pragma unroll
    for (int o = 0; o < C8; o += 4) {
        *(float4*)&qdst[o] = make_float4(qa[o], qa[o + 1], qa[o + 2], qa[o + 3]);
        *(float4*)&kdst[o] = make_float4(ka[o], ka[o + 1], ka[o + 2], ka[o + 3]);
    }
}

// ------------------------------------------------------------------
// Kernel 2: logits + softmax. Thread = query row m. Stores UNNORMALIZED
// exp into g_e transposed ([n][m]) and row sums into g_z.
// ------------------------------------------------------------------
__global__ void __launch_bounds__(256) attn_kernel()
{
    __shared__ float skk[NT * C8];    // 32 KB
    int w = blockIdx.x, m = threadIdx.x;
    const float* kp = g_k + (size_t)w * NT * C8;
    for (int i = m; i < NT * C8; i += 256) skk[i] = kp[i];
    __syncthreads();

    float4 qv[8];
    const float4* qp = (const float4*)(g_q + (size_t)w * NT * C8 + m * C8);
#pragma unroll
    for (int q = 0; q < 8; q++) qv[q] = qp[q];

    float mx = -1e30f;
    for (int n = 0; n < NT; n++) {
        const float4* kk4 = (const float4*)&skk[n * C8];
        float d = 0.f;
#pragma unroll
        for (int q = 0; q < 8; q++) {
            float4 kv = kk4[q];
            d = fmaf(qv[q].x, kv.x, d); d = fmaf(qv[q].y, kv.y, d);
            d = fmaf(qv[q].z, kv.z, d); d = fmaf(qv[q].w, kv.w, d);
        }
        mx = fmaxf(mx, d);
    }
    float z = 0.f;
    float* ed = g_e + (size_t)w * NT * NT;
    for (int n = 0; n < NT; n++) {
        const float4* kk4 = (const float4*)&skk[n * C8];
        float d = 0.f;
#pragma unroll
        for (int q = 0; q < 8; q++) {
            float4 kv = kk4[q];
            d = fmaf(qv[q].x, kv.x, d); d = fmaf(qv[q].y, kv.y, d);
            d = fmaf(qv[q].z, kv.z, d); d = fmaf(qv[q].w, kv.w, d);
        }
        float e = __expf(d - mx);
        z += e;
        ed[n * NT + m] = e;       // coalesced across m
    }
    g_z[w * NT + m] = z;
}

// ------------------------------------------------------------------
// Kernel 3a: t[ch][m] = sum_n xw[ch][n] * E[n][m]   (per window, tiled GEMM)
// grid (16 tiles, 512 windows), 256 threads, 64x64 tile, 4x4 micro
// ------------------------------------------------------------------
__global__ void __launch_bounds__(256) gemm_t_kernel(const float* __restrict__ x)
{
    __shared__ float As[16][68];
    __shared__ float Bs[16][64];
    int w = blockIdx.y;
    int tile = blockIdx.x;
    int ch0 = (tile >> 2) * 64, m0 = (tile & 3) * 64;
    int tid = threadIdx.x, ty = tid >> 4, tx = tid & 15;
    int b = w >> 6, r = w & 63, ih = r >> 3, iw = r & 7;
    const float* xb = x + (size_t)b * CC * HH * WWD + ih * GG * WWD + iw * GG;
    const float* eb = g_e + (size_t)w * NT * NT;

    float acc[4][4];
#pragma unroll
    for (int i = 0; i < 4; i++)
#pragma unroll
        for (int j = 0; j < 4; j++) acc[i][j] = 0.f;

    for (int k0 = 0; k0 < NT; k0 += 16) {
        int gyk = k0 >> 4;
#pragma unroll
        for (int j = 0; j < 4; j++) {
            int i = tid + j * 256;
            int ch = i >> 4, kk = i & 15;
            As[kk][ch] = xb[(size_t)(ch0 + ch) * HH * WWD + gyk * WWD + kk];
            int mm = i & 63, k2 = i >> 6;
            Bs[k2][mm] = eb[(size_t)(k0 + k2) * NT + m0 + mm];
        }
        __syncthreads();
#pragma unroll
        for (int k = 0; k < 16; k++) {
            float4 a = *(const float4*)&As[k][ty * 4];
            float4 bv = *(const float4*)&Bs[k][tx * 4];
            float av[4] = {a.x, a.y, a.z, a.w};
            float bw[4] = {bv.x, bv.y, bv.z, bv.w};
#pragma unroll
            for (int i = 0; i < 4; i++)
#pragma unroll
                for (int j = 0; j < 4; j++) acc[i][j] = fmaf(av[i], bw[j], acc[i][j]);
        }
        __syncthreads();
    }
    float* tdst = g_t + (size_t)w * NT * NT;
#pragma unroll
    for (int i = 0; i < 4; i++) {
        int ch = ch0 + ty * 4 + i;
        *(float4*)&tdst[(size_t)ch * NT + m0 + tx * 4] =
            make_float4(acc[i][0], acc[i][1], acc[i][2], acc[i][3]);
    }
}

// ------------------------------------------------------------------
// Kernel 3b: out = Wv @ t ; aw = gamma*out/Z + xw ; scatter to xa (NCHW)
// ------------------------------------------------------------------
__global__ void __launch_bounds__(256) gemm_o_kernel(const float* __restrict__ x,
                                                     const float* __restrict__ Wv,
                                                     const float* __restrict__ gamma)
{
    __shared__ float As[16][68];
    __shared__ float Bs[16][64];
    int w = blockIdx.y;
    int tile = blockIdx.x;
    int c0 = (tile >> 2) * 64, m0 = (tile & 3) * 64;
    int tid = threadIdx.x, ty = tid >> 4, tx = tid & 15;
    int b = w >> 6, r = w & 63, ih = r >> 3, iw = r & 7;
    const float* tb = g_t + (size_t)w * NT * NT;

    float acc[4][4];
#pragma unroll
    for (int i = 0; i < 4; i++)
#pragma unroll
        for (int j = 0; j < 4; j++) acc[i][j] = 0.f;

    for (int k0 = 0; k0 < CC; k0 += 16) {
#pragma unroll
        for (int j = 0; j < 4; j++) {
            int i = tid + j * 256;
            int ch = i >> 4, kk = i & 15;
            As[kk][ch] = Wv[(size_t)(c0 + ch) * CC + k0 + kk];
            int mm = i & 63, k2 = i >> 6;
            Bs[k2][mm] = tb[(size_t)(k0 + k2) * NT + m0 + mm];
        }
        __syncthreads();
#pragma unroll
        for (int k = 0; k < 16; k++) {
            float4 a = *(const float4*)&As[k][ty * 4];
            float4 bv = *(const float4*)&Bs[k][tx * 4];
            float av[4] = {a.x, a.y, a.z, a.w};
            float bw[4] = {bv.x, bv.y, bv.z, bv.w};
#pragma unroll
            for (int i = 0; i < 4; i++)
#pragma unroll
                for (int j = 0; j < 4; j++) acc[i][j] = fmaf(av[i], bw[j], acc[i][j]);
        }
        __syncthreads();
    }

    float g = __ldg(gamma);
    float zr[4];
#pragma unroll
    for (int j = 0; j < 4; j++) zr[j] = 1.f / g_z[w * NT + m0 + tx * 4 + j];

    const float* xb = x + (size_t)b * CC * HH * WWD + ih * GG * WWD + iw * GG;
#pragma unroll
    for (int i = 0; i < 4; i++) {
        int c = c0 + ty * 4 + i;
#pragma unroll
        for (int j = 0; j < 4; j++) {
            int m = m0 + tx * 4 + j;
            int gy = m >> 4, gx = m & 15;
            size_t poff = (size_t)c * HH * WWD + gy * WWD + gx;
            float val = g * acc[i][j] * zr[j] + xb[poff];
            g_xa[(size_t)(b * CC + c) * HH * WWD + (ih * GG + gy) * WWD + iw * GG + gx] = val;
        }
    }
}

// ------------------------------------------------------------------
// Kernel 4: fused FFN (W1 -> GELU -> W2) + LN1 + residual + LN2 + residual.
// Block = one image row (128 pixels, all 256 channels). 512 threads.
// h1 never leaves shared memory; y never leaves registers.
// ------------------------------------------------------------------
__device__ __forceinline__ float gelu_exact(float v) { return v * normcdff(v); }

#define FFN_SMEM_FLOATS (32768 + 4608 + 8192 + 8192)

__global__ void __launch_bounds__(512) ffn_kernel(const float* __restrict__ W1,
                                                  const float* __restrict__ b1,
                                                  const float* __restrict__ W2,
                                                  const float* __restrict__ b2,
                                                  const float* __restrict__ ln1w,
                                                  const float* __restrict__ ln1b,
                                                  const float* __restrict__ ln2w,
                                                  const float* __restrict__ ln2b,
                                                  float* __restrict__ out)
{
    extern __shared__ float sm[];
    float* xs  = sm;                   // [256][128]  xa tile       (32768)
    float* hs  = sm + 32768;           // [128][36]   gelu chunk    (4608)
    float* sW1 = sm + 32768 + 4608;    // [32][256]                 (8192)
    float* sW2 = sW1 + 8192;           // [256][32]                 (8192)
    float* red = sW1;                  // reused for LN reductions

    int blk = blockIdx.x;
    int b = blk >> 7, yy = blk & 127;
    int tid = threadIdx.x;
    int p = tid & 127, cg = tid >> 7;        // cg in [0,4): owns channels [cg*64, cg*64+64)

    for (int i = tid; i < CC * WWD; i += 512) {
        int c = i >> 7, pp = i & 127;
        xs[c * 128 + pp] = g_xa[(size_t)(b * CC + c) * HH * WWD + yy * WWD + pp];
    }
    float yacc[64];
#pragma unroll
    for (int i = 0; i < 64; i++) yacc[i] = 0.f;
    __syncthreads();

    for (int f0 = 0; f0 < FF; f0 += 32) {
        for (int i = tid; i < 32 * CC; i += 512) sW1[i] = W1[(size_t)f0 * CC + i];
        for (int i = tid; i < CC * 32; i += 512) {
            int c = i >> 5, fl = i & 31;
            sW2[i] = W2[(size_t)c * FF + f0 + fl];
        }
        __syncthreads();

        // ---- h chunk: each thread computes 8 f's for its pixel ----
        float hac[8];
#pragma unroll
        for (int j = 0; j < 8; j++) hac[j] = b1[f0 + cg * 8 + j];
        for (int c = 0; c < CC; c += 4) {
            float x0 = xs[(c + 0) * 128 + p];
            float x1 = xs[(c + 1) * 128 + p];
            float x2v = xs[(c + 2) * 128 + p];
            float x3 = xs[(c + 3) * 128 + p];
#pragma unroll
            for (int j = 0; j < 8; j++) {
                float4 wv = *(const float4*)&sW1[(cg * 8 + j) * CC + c];
                hac[j] = fmaf(wv.x, x0, fmaf(wv.y, x1, fmaf(wv.z, x2v, fmaf(wv.w, x3, hac[j]))));
            }
        }
#pragma unroll
        for (int j = 0; j < 8; j++) hs[p * 36 + cg * 8 + j] = gelu_exact(hac[j]);
        __syncthreads();

        // ---- y accumulate: thread owns 64 channels for pixel p ----
        float4 hq[8];
#pragma unroll
        for (int q = 0; q < 8; q++) hq[q] = *(const float4*)&hs[p * 36 + q * 4];
#pragma unroll
        for (int cl = 0; cl < 64; cl++) {
            int c = cg * 64 + cl;
            float s = 0.f;
#pragma unroll
            for (int q = 0; q < 8; q++) {
                float4 wv = *(const float4*)&sW2[c * 32 + q * 4];
                s = fmaf(wv.x, hq[q].x, fmaf(wv.y, hq[q].y, fmaf(wv.z, hq[q].z, fmaf(wv.w, hq[q].w, s))));
            }
            yacc[cl] += s;
        }
        __syncthreads();
    }

    // ---- bias + LN1 stats ----
    float s1 = 0.f, s2 = 0.f;
#pragma unroll
    for (int cl = 0; cl < 64; cl++) {
        int c = cg * 64 + cl;
        yacc[cl] += b2[c];
        s1 += yacc[cl];
        s2 += yacc[cl] * yacc[cl];
    }
    red[cg * 128 + p] = s1;
    red[512 + cg * 128 + p] = s2;
    __syncthreads();
    float S1 = red[p] + red[128 + p] + red[256 + p] + red[384 + p];
    float S2 = red[512 + p] + red[640 + p] + red[768 + p] + red[896 + p];
    float mu = S1 * (1.f / 256.f);
    float rstd = rsqrtf(S2 * (1.f / 256.f) - mu * mu + 1e-5f);

    // ---- x2 = xa + LN1(y) ; LN2 stats ----
    float t1 = 0.f, t2 = 0.f;
#pragma unroll
    for (int cl = 0; cl < 64; cl++) {
        int c = cg * 64 + cl;
        float lnv = (yacc[cl] - mu) * rstd * ln1w[c] + ln1b[c];
        float x2v = xs[c * 128 + p] + lnv;
        yacc[cl] = x2v;
        t1 += x2v;
        t2 += x2v * x2v;
    }
    __syncthreads();
    red[cg * 128 + p] = t1;
    red[512 + cg * 128 + p] = t2;
    __syncthreads();
    float T1 = red[p] + red[128 + p] + red[256 + p] + red[384 + p];
    float T2 = red[512 + p] + red[640 + p] + red[768 + p] + red[896 + p];
    float mu2 = T1 * (1.f / 256.f);
    float rstd2 = rsqrtf(T2 * (1.f / 256.f) - mu2 * mu2 + 1e-5f);

    size_t obase = (size_t)b * CC * HH * WWD + (size_t)yy * WWD + p;
#pragma unroll
    for (int cl = 0; cl < 64; cl++) {
        int c = cg * 64 + cl;
        float v = yacc[cl];
        out[obase + (size_t)c * HH * WWD] = v + (v - mu2) * rstd2 * ln2w[c] + ln2b[c];
    }
}

// ------------------------------------------------------------------
extern "C" void kernel_launch(void* const* d_in, const int* in_sizes, int n_in,
                              void* d_out, int out_size)
{
    const float* x    = (const float*)d_in[0];
    const float* Wq   = (const float*)d_in[1];
    const float* Wk   = (const float*)d_in[2];
    const float* Wv   = (const float*)d_in[3];
    const float* gam  = (const float*)d_in[4];
    const float* W1   = (const float*)d_in[5];
    const float* b1   = (const float*)d_in[6];
    const float* W2   = (const float*)d_in[7];
    const float* b2   = (const float*)d_in[8];
    const float* ln1w = (const float*)d_in[9];
    const float* ln1b = (const float*)d_in[10];
    const float* ln2w = (const float*)d_in[11];
    const float* ln2b = (const float*)d_in[12];
    float* out = (float*)d_out;

    cudaFuncSetAttribute(qk_kernel, cudaFuncAttributeMaxDynamicSharedMemorySize, 2 * C8 * CC * 4);
    cudaFuncSetAttribute(ffn_kernel, cudaFuncAttributeMaxDynamicSharedMemorySize, FFN_SMEM_FLOATS * 4);

    qk_kernel<<<NWIN, 256, 2 * C8 * CC * 4>>>(x, Wq, Wk);
    attn_kernel<<<NWIN, 256>>>();
    gemm_t_kernel<<<dim3(16, NWIN), 256>>>(x);
    gemm_o_kernel<<<dim3(16, NWIN), 256>>>(x, Wv, gam);
    ffn_kernel<<<BQ * HH, 512, FFN_SMEM_FLOATS * 4>>>(W1, b1, W2, b2, ln1w, ln1b, ln2w, ln2b, out);
}

// round 3
// speedup vs baseline: 2.3754x; 2.3754x over previous
#include <cuda_runtime.h>
#include <math.h>
#include <stdint.h>

#define BQ   8
#define CC   256
#define HH   128
#define WWD  128
#define GG   16
#define NWIN 512
#define NT   256
#define C8   32
#define FF   1024

// ---------------- device scratch ----------------
__device__ __align__(128) float g_q[(size_t)NWIN * NT * C8];
__device__ __align__(128) float g_k[(size_t)NWIN * NT * C8];
__device__ __align__(128) float g_e[(size_t)NWIN * NT * NT];
__device__ __align__(128) float g_z[(size_t)NWIN * NT];
__device__ __align__(128) float g_t[(size_t)NWIN * NT * NT];
__device__ __align__(128) float g_xa[(size_t)BQ * CC * HH * WWD];

// ================= helpers =================
__device__ __forceinline__ uint32_t smem_u32(const void* p) {
    uint32_t a;
    asm("{ .reg .u64 t; cvta.to.shared.u64 t, %1; cvt.u32.u64 %0, t; }" : "=r"(a) : "l"(p));
    return a;
}
__device__ __forceinline__ float tf32r(float v) {
    uint32_t r; asm("cvt.rna.tf32.f32 %0, %1;" : "=r"(r) : "f"(v));
    return __uint_as_float(r);
}
__device__ __forceinline__ void mma_tf32(float* d, uint32_t a0, uint32_t a1, uint32_t a2, uint32_t a3,
                                         uint32_t b0, uint32_t b1) {
    asm volatile(
        "mma.sync.aligned.m16n8k8.row.col.f32.tf32.tf32.f32 "
        "{%0,%1,%2,%3}, {%4,%5,%6,%7}, {%8,%9}, {%0,%1,%2,%3};"
        : "+f"(d[0]), "+f"(d[1]), "+f"(d[2]), "+f"(d[3])
        : "r"(a0), "r"(a1), "r"(a2), "r"(a3), "r"(b0), "r"(b1));
}
#define CP16(dst, src) asm volatile("cp.async.cg.shared.global [%0], [%1], 16;" :: "r"(dst), "l"(src))
#define CP_COMMIT()    asm volatile("cp.async.commit_group;" ::: "memory")
#define CP_WAIT1()     asm volatile("cp.async.wait_group 1;" ::: "memory")

__device__ __forceinline__ float gelu_exact(float v) { return v * normcdff(v); }

// ------------------------------------------------------------------
// Kernel 1: q/k projections per window
// ------------------------------------------------------------------
__global__ void __launch_bounds__(256) qk_kernel(const float* __restrict__ x,
                                                 const float* __restrict__ Wq,
                                                 const float* __restrict__ Wk)
{
    extern __shared__ float s[];
    float* sq = s;
    float* sk = s + C8 * CC;
    int tid = threadIdx.x;
    for (int i = tid; i < C8 * CC; i += 256) { sq[i] = Wq[i]; sk[i] = Wk[i]; }
    __syncthreads();

    int w = blockIdx.x;
    int b = w >> 6, r = w & 63, ih = r >> 3, iw = r & 7;
    int n = tid, gy = n >> 4, gx = n & 15;
    const float* xp = x + (size_t)b * CC * HH * WWD + (ih * GG + gy) * WWD + iw * GG + gx;

    float qa[C8], ka[C8];
#pragma unroll
    for (int o = 0; o < C8; o++) { qa[o] = 0.f; ka[o] = 0.f; }

    for (int c = 0; c < CC; c += 4) {
        float v0 = xp[(size_t)(c + 0) * HH * WWD];
        float v1 = xp[(size_t)(c + 1) * HH * WWD];
        float v2 = xp[(size_t)(c + 2) * HH * WWD];
        float v3 = xp[(size_t)(c + 3) * HH * WWD];
#pragma unroll
        for (int o = 0; o < C8; o++) {
            float4 a = *(const float4*)&sq[o * CC + c];
            qa[o] = fmaf(a.x, v0, fmaf(a.y, v1, fmaf(a.z, v2, fmaf(a.w, v3, qa[o]))));
            float4 bb = *(const float4*)&sk[o * CC + c];
            ka[o] = fmaf(bb.x, v0, fmaf(bb.y, v1, fmaf(bb.z, v2, fmaf(bb.w, v3, ka[o]))));
        }
    }
    float* qdst = g_q + (size_t)w * NT * C8 + n * C8;
    float* kdst = g_k + (size_t)w * NT * C8 + n * C8;
#pragma unroll
    for (int o = 0; o < C8; o += 4) {
        *(float4*)&qdst[o] = make_float4(qa[o], qa[o + 1], qa[o + 2], qa[o + 3]);
        *(float4*)&kdst[o] = make_float4(ka[o], ka[o + 1], ka[o + 2], ka[o + 3]);
    }
}

// ------------------------------------------------------------------
// Kernel 2: logits + softmax (unnormalized exp + row sums)
// ------------------------------------------------------------------
__global__ void __launch_bounds__(256) attn_kernel()
{
    __shared__ float skk[NT * C8];
    int w = blockIdx.x, m = threadIdx.x;
    const float* kp = g_k + (size_t)w * NT * C8;
    for (int i = m; i < NT * C8; i += 256) skk[i] = kp[i];
    __syncthreads();

    float4 qv[8];
    const float4* qp = (const float4*)(g_q + (size_t)w * NT * C8 + m * C8);
#pragma unroll
    for (int q = 0; q < 8; q++) qv[q] = qp[q];

    float mx = -1e30f;
    for (int n = 0; n < NT; n++) {
        const float4* kk4 = (const float4*)&skk[n * C8];
        float d = 0.f;
#pragma unroll
        for (int q = 0; q < 8; q++) {
            float4 kv = kk4[q];
            d = fmaf(qv[q].x, kv.x, d); d = fmaf(qv[q].y, kv.y, d);
            d = fmaf(qv[q].z, kv.z, d); d = fmaf(qv[q].w, kv.w, d);
        }
        mx = fmaxf(mx, d);
    }
    float z = 0.f;
    float* ed = g_e + (size_t)w * NT * NT;
    for (int n = 0; n < NT; n++) {
        const float4* kk4 = (const float4*)&skk[n * C8];
        float d = 0.f;
#pragma unroll
        for (int q = 0; q < 8; q++) {
            float4 kv = kk4[q];
            d = fmaf(qv[q].x, kv.x, d); d = fmaf(qv[q].y, kv.y, d);
            d = fmaf(qv[q].z, kv.z, d); d = fmaf(qv[q].w, kv.w, d);
        }
        float e = __expf(d - mx);
        z += e;
        ed[n * NT + m] = e;
    }
    g_z[w * NT + m] = z;
}

// ------------------------------------------------------------------
// Kernel 3a: t = xw @ E
// ------------------------------------------------------------------
__global__ void __launch_bounds__(256) gemm_t_kernel(const float* __restrict__ x)
{
    __shared__ float As[16][68];
    __shared__ float Bs[16][64];
    int w = blockIdx.y;
    int tile = blockIdx.x;
    int ch0 = (tile >> 2) * 64, m0 = (tile & 3) * 64;
    int tid = threadIdx.x, ty = tid >> 4, tx = tid & 15;
    int b = w >> 6, r = w & 63, ih = r >> 3, iw = r & 7;
    const float* xb = x + (size_t)b * CC * HH * WWD + ih * GG * WWD + iw * GG;
    const float* eb = g_e + (size_t)w * NT * NT;

    float acc[4][4];
#pragma unroll
    for (int i = 0; i < 4; i++)
#pragma unroll
        for (int j = 0; j < 4; j++) acc[i][j] = 0.f;

    for (int k0 = 0; k0 < NT; k0 += 16) {
        int gyk = k0 >> 4;
#pragma unroll
        for (int j = 0; j < 4; j++) {
            int i = tid + j * 256;
            int ch = i >> 4, kk = i & 15;
            As[kk][ch] = xb[(size_t)(ch0 + ch) * HH * WWD + gyk * WWD + kk];
            int mm = i & 63, k2 = i >> 6;
            Bs[k2][mm] = eb[(size_t)(k0 + k2) * NT + m0 + mm];
        }
        __syncthreads();
#pragma unroll
        for (int k = 0; k < 16; k++) {
            float4 a = *(const float4*)&As[k][ty * 4];
            float4 bv = *(const float4*)&Bs[k][tx * 4];
            float av[4] = {a.x, a.y, a.z, a.w};
            float bw[4] = {bv.x, bv.y, bv.z, bv.w};
#pragma unroll
            for (int i = 0; i < 4; i++)
#pragma unroll
                for (int j = 0; j < 4; j++) acc[i][j] = fmaf(av[i], bw[j], acc[i][j]);
        }
        __syncthreads();
    }
    float* tdst = g_t + (size_t)w * NT * NT;
#pragma unroll
    for (int i = 0; i < 4; i++) {
        int ch = ch0 + ty * 4 + i;
        *(float4*)&tdst[(size_t)ch * NT + m0 + tx * 4] =
            make_float4(acc[i][0], acc[i][1], acc[i][2], acc[i][3]);
    }
}

// ------------------------------------------------------------------
// Kernel 3b: out = Wv @ t ; residual + scatter
// ------------------------------------------------------------------
__global__ void __launch_bounds__(256) gemm_o_kernel(const float* __restrict__ x,
                                                     const float* __restrict__ Wv,
                                                     const float* __restrict__ gamma)
{
    __shared__ float As[16][68];
    __shared__ float Bs[16][64];
    int w = blockIdx.y;
    int tile = blockIdx.x;
    int c0 = (tile >> 2) * 64, m0 = (tile & 3) * 64;
    int tid = threadIdx.x, ty = tid >> 4, tx = tid & 15;
    int b = w >> 6, r = w & 63, ih = r >> 3, iw = r & 7;
    const float* tb = g_t + (size_t)w * NT * NT;

    float acc[4][4];
#pragma unroll
    for (int i = 0; i < 4; i++)
#pragma unroll
        for (int j = 0; j < 4; j++) acc[i][j] = 0.f;

    for (int k0 = 0; k0 < CC; k0 += 16) {
#pragma unroll
        for (int j = 0; j < 4; j++) {
            int i = tid + j * 256;
            int ch = i >> 4, kk = i & 15;
            As[kk][ch] = Wv[(size_t)(c0 + ch) * CC + k0 + kk];
            int mm = i & 63, k2 = i >> 6;
            Bs[k2][mm] = tb[(size_t)(k0 + k2) * NT + m0 + mm];
        }
        __syncthreads();
#pragma unroll
        for (int k = 0; k < 16; k++) {
            float4 a = *(const float4*)&As[k][ty * 4];
            float4 bv = *(const float4*)&Bs[k][tx * 4];
            float av[4] = {a.x, a.y, a.z, a.w};
            float bw[4] = {bv.x, bv.y, bv.z, bv.w};
#pragma unroll
            for (int i = 0; i < 4; i++)
#pragma unroll
                for (int j = 0; j < 4; j++) acc[i][j] = fmaf(av[i], bw[j], acc[i][j]);
        }
        __syncthreads();
    }

    float g = __ldg(gamma);
    float zr[4];
#pragma unroll
    for (int j = 0; j < 4; j++) zr[j] = 1.f / g_z[w * NT + m0 + tx * 4 + j];

    const float* xb = x + (size_t)b * CC * HH * WWD + ih * GG * WWD + iw * GG;
#pragma unroll
    for (int i = 0; i < 4; i++) {
        int c = c0 + ty * 4 + i;
#pragma unroll
        for (int j = 0; j < 4; j++) {
            int m = m0 + tx * 4 + j;
            int gy = m >> 4, gx = m & 15;
            size_t poff = (size_t)c * HH * WWD + gy * WWD + gx;
            float val = g * acc[i][j] * zr[j] + xb[poff];
            g_xa[(size_t)(b * CC + c) * HH * WWD + (ih * GG + gy) * WWD + iw * GG + gx] = val;
        }
    }
}

// ------------------------------------------------------------------
// Kernel 4: mma.sync tf32 FFN + LN1/LN2 + residuals
// CTA = one image row (128 px), 256 threads (8 warps).
// smem (floats): xs [256][132] @0 (33792) | hs [32][132] @33792 (4224)
//                w1s [32][260] @38016 (8320) | w2s [256][36] @46336 (9216)
// ys (epilogue) aliases xs; red aliases hs.
// ------------------------------------------------------------------
#define XS_OFF 0
#define HS_OFF 33792
#define W1_OFF 38016
#define W2_OFF 46336
#define FFN_SMEM_FLOATS 55552
#define FFN_SMEM_BYTES (FFN_SMEM_FLOATS * 4)

__global__ void __launch_bounds__(256) ffn_mma_kernel(const float* __restrict__ W1,
                                                      const float* __restrict__ b1,
                                                      const float* __restrict__ W2,
                                                      const float* __restrict__ b2,
                                                      const float* __restrict__ ln1w,
                                                      const float* __restrict__ ln1b,
                                                      const float* __restrict__ ln2w,
                                                      const float* __restrict__ ln2b,
                                                      float* __restrict__ out)
{
    extern __shared__ __align__(16) float sm[];
    float* xs  = sm + XS_OFF;
    float* hs  = sm + HS_OFF;
    float* w1s = sm + W1_OFF;
    float* w2s = sm + W2_OFF;
    const uint32_t w1u = smem_u32(w1s);
    const uint32_t w2u = smem_u32(w2s);

    const int tid = threadIdx.x, lane = tid & 31, wp = tid >> 5;
    const int g = lane >> 2, t = lane & 3;
    const int blk = blockIdx.x, b = blk >> 7, row = blk & 127;

    // warp mapping GEMM1: D1[32f][128px]: 2 warps along f x 4 along px
    const int fr0 = (wp >> 2) * 16;
    const int px0 = (wp & 3) * 32;
    // warp mapping GEMM2: D2t[128px][256c]: 4 along px x 2 along c
    const int pxm0 = (wp & 3) * 32;
    const int c0w = (wp >> 2) * 128;

    // ---- issue weight prefetch for ft=0 ----
    {
        // W1 tile [32f][256c] -> w1s[f][c] stride 260
        for (int j = 0; j < 8; j++) {
            int id = tid + j * 256;
            int f = id >> 6, seg = id & 63;
            CP16(w1u + (uint32_t)(f * 260 + seg * 4) * 4u,
                 W1 + (size_t)f * CC + seg * 4);
        }
        CP_COMMIT();
        // W2 tile: w2s[c][f] stride 36, source W2[c][0..31]
        for (int j = 0; j < 8; j++) {
            int id = tid + j * 256;
            int c = id >> 3, seg = id & 7;
            CP16(w2u + (uint32_t)(c * 36 + seg * 4) * 4u,
                 W2 + (size_t)c * FF + seg * 4);
        }
        CP_COMMIT();
    }

    // ---- stage xa row into xs (tf32-rounded) ----
    {
        const float* xab = g_xa + (size_t)b * CC * HH * WWD + (size_t)row * WWD;
        int px = tid & 127, ch = tid >> 7;
#pragma unroll 8
        for (int it = 0; it < 128; it++) {
            int c = ch + it * 2;
            xs[c * 132 + px] = tf32r(xab[(size_t)c * HH * WWD + px]);
        }
    }

    float yacc[2][16][4];
#pragma unroll
    for (int mf = 0; mf < 2; mf++)
#pragma unroll
        for (int nf = 0; nf < 16; nf++)
#pragma unroll
            for (int r = 0; r < 4; r++) yacc[mf][nf][r] = 0.f;

    for (int ft = 0; ft < 32; ft++) {
        const int ftb = ft * 32;
        CP_WAIT1();            // W1(ft) complete (W2(ft) may still be in flight)
        __syncthreads();

        // ================= GEMM1: D1[f][px] = W1 @ xa =================
        float d1[4][4];
#pragma unroll
        for (int nf = 0; nf < 4; nf++)
#pragma unroll
            for (int r = 0; r < 4; r++) d1[nf][r] = 0.f;

        {
            const float* wr0 = w1s + (fr0 + g) * 260;
            const float* wr1 = wr0 + 8 * 260;
            const float* xb0 = xs + t * 132 + px0 + g;
#pragma unroll
            for (int ks = 0; ks < 32; ks++) {
                int k = ks * 8;
                uint32_t a0 = __float_as_uint(wr0[k + t]);
                uint32_t a1 = __float_as_uint(wr1[k + t]);
                uint32_t a2 = __float_as_uint(wr0[k + t + 4]);
                uint32_t a3 = __float_as_uint(wr1[k + t + 4]);
                const float* xk = xb0 + k * 132;
#pragma unroll
                for (int nf = 0; nf < 4; nf++) {
                    uint32_t b0 = __float_as_uint(xk[nf * 8]);
                    uint32_t b1 = __float_as_uint(xk[4 * 132 + nf * 8]);
                    mma_tf32(d1[nf], a0, a1, a2, a3, b0, b1);
                }
            }
        }
        __syncthreads();       // all warps done reading w1s
        if (ft < 31) {         // prefetch W1(ft+1)
            const float* src = W1 + (size_t)(ftb + 32) * CC;
            for (int j = 0; j < 8; j++) {
                int id = tid + j * 256;
                int f = id >> 6, seg = id & 63;
                CP16(w1u + (uint32_t)(f * 260 + seg * 4) * 4u,
                     src + (size_t)f * CC + seg * 4);
            }
        }
        CP_COMMIT();

        // ---- GELU(D1 + b1) -> hs ----
        {
            float b1a = __ldg(&b1[ftb + fr0 + g]);
            float b1b = __ldg(&b1[ftb + fr0 + g + 8]);
#pragma unroll
            for (int nf = 0; nf < 4; nf++) {
                int px = px0 + nf * 8 + 2 * t;
                float2 v01 = make_float2(tf32r(gelu_exact(d1[nf][0] + b1a)),
                                         tf32r(gelu_exact(d1[nf][1] + b1a)));
                float2 v23 = make_float2(tf32r(gelu_exact(d1[nf][2] + b1b)),
                                         tf32r(gelu_exact(d1[nf][3] + b1b)));
                *(float2*)&hs[(fr0 + g) * 132 + px] = v01;
                *(float2*)&hs[(fr0 + g + 8) * 132 + px] = v23;
            }
        }
        CP_WAIT1();            // W2(ft) complete (W1(ft+1) still in flight)
        __syncthreads();       // hs written by all warps + w2s visible

        // ================= GEMM2: yacc[px][c] += h^T @ W2^T =================
        {
#pragma unroll
            for (int ks = 0; ks < 4; ks++) {
                int k = ks * 8;
                uint32_t am[2][4];
#pragma unroll
                for (int mf = 0; mf < 2; mf++) {
                    const float* hb = hs + (k + t) * 132 + pxm0 + 16 * mf + g;
                    am[mf][0] = __float_as_uint(hb[0]);
                    am[mf][1] = __float_as_uint(hb[8]);
                    am[mf][2] = __float_as_uint(hb[4 * 132]);
                    am[mf][3] = __float_as_uint(hb[4 * 132 + 8]);
                }
#pragma unroll
                for (int nf = 0; nf < 16; nf++) {
                    const float* wb = w2s + (c0w + nf * 8 + g) * 36 + k + t;
                    uint32_t b0 = __float_as_uint(wb[0]);
                    uint32_t b1 = __float_as_uint(wb[4]);
                    mma_tf32(yacc[0][nf], am[0][0], am[0][1], am[0][2], am[0][3], b0, b1);
                    mma_tf32(yacc[1][nf], am[1][0], am[1][1], am[1][2], am[1][3], b0, b1);
                }
            }
        }
        __syncthreads();       // all warps done reading w2s (and hs)
        if (ft < 31) {         // prefetch W2(ft+1)
            const float* src = W2 + (size_t)(ftb + 32);
            for (int j = 0; j < 8; j++) {
                int id = tid + j * 256;
                int c = id >> 3, seg = id & 7;
                CP16(w2u + (uint32_t)(c * 36 + seg * 4) * 4u,
                     src + (size_t)c * FF + seg * 4);
            }
        }
        CP_COMMIT();
    }
    __syncthreads();

    // ---- store yacc + b2 into ys [128px][260] (aliases xs) ----
    float* ys = sm;
#pragma unroll
    for (int nf = 0; nf < 16; nf++) {
        int c = c0w + nf * 8 + 2 * t;
        float b2a = __ldg(&b2[c]);
        float b2b = __ldg(&b2[c + 1]);
#pragma unroll
        for (int mf = 0; mf < 2; mf++) {
            int pxr = pxm0 + 16 * mf + g;
            *(float2*)&ys[pxr * 260 + c] =
                make_float2(yacc[mf][nf][0] + b2a, yacc[mf][nf][1] + b2b);
            *(float2*)&ys[(pxr + 8) * 260 + c] =
                make_float2(yacc[mf][nf][2] + b2a, yacc[mf][nf][3] + b2b);
        }
    }
    __syncthreads();

    // ---- LN1 + residual + LN2 + residual ----
    int px = tid >> 1, hf = tid & 1;
    float* yrow = ys + px * 260 + hf * 128;
    float* red = hs;   // reuse

    float s1 = 0.f, s2 = 0.f;
#pragma unroll 8
    for (int i = 0; i < 128; i += 4) {
        float4 v = *(float4*)&yrow[i];
        s1 += v.x + v.y + v.z + v.w;
        s2 += v.x * v.x + v.y * v.y + v.z * v.z + v.w * v.w;
    }
    red[tid] = s1; red[512 + tid] = s2;
    __syncthreads();
    float mu = (red[px * 2] + red[px * 2 + 1]) * (1.f / 256.f);
    float va = (red[512 + px * 2] + red[512 + px * 2 + 1]) * (1.f / 256.f);
    float rstd = rsqrtf(va - mu * mu + 1e-5f);

    const float* xsrc = g_xa + ((size_t)(b * CC) + hf * 128) * HH * WWD + (size_t)row * WWD + px;
    float t1 = 0.f, t2 = 0.f;
    for (int i = 0; i < 128; i++) {
        int c = hf * 128 + i;
        float x2v = xsrc[(size_t)i * HH * WWD] + (yrow[i] - mu) * rstd * ln1w[c] + ln1b[c];
        yrow[i] = x2v;
        t1 += x2v; t2 += x2v * x2v;
    }
    __syncthreads();
    red[tid] = t1; red[512 + tid] = t2;
    __syncthreads();
    float mu2 = (red[px * 2] + red[px * 2 + 1]) * (1.f / 256.f);
    float va2 = (red[512 + px * 2] + red[512 + px * 2 + 1]) * (1.f / 256.f);
    float rstd2 = rsqrtf(va2 - mu2 * mu2 + 1e-5f);

    float* op = out + ((size_t)(b * CC) + hf * 128) * HH * WWD + (size_t)row * WWD + px;
    for (int i = 0; i < 128; i++) {
        int c = hf * 128 + i;
        float v = yrow[i];
        op[(size_t)i * HH * WWD] = v + (v - mu2) * rstd2 * ln2w[c] + ln2b[c];
    }
}

// ------------------------------------------------------------------
extern "C" void kernel_launch(void* const* d_in, const int* in_sizes, int n_in,
                              void* d_out, int out_size)
{
    const float* x    = (const float*)d_in[0];
    const float* Wq   = (const float*)d_in[1];
    const float* Wk   = (const float*)d_in[2];
    const float* Wv   = (const float*)d_in[3];
    const float* gam  = (const float*)d_in[4];
    const float* W1   = (const float*)d_in[5];
    const float* b1   = (const float*)d_in[6];
    const float* W2   = (const float*)d_in[7];
    const float* b2   = (const float*)d_in[8];
    const float* ln1w = (const float*)d_in[9];
    const float* ln1b = (const float*)d_in[10];
    const float* ln2w = (const float*)d_in[11];
    const float* ln2b = (const float*)d_in[12];
    float* out = (float*)d_out;

    cudaFuncSetAttribute(qk_kernel, cudaFuncAttributeMaxDynamicSharedMemorySize, 2 * C8 * CC * 4);
    cudaFuncSetAttribute(ffn_mma_kernel, cudaFuncAttributeMaxDynamicSharedMemorySize, FFN_SMEM_BYTES);

    qk_kernel<<<NWIN, 256, 2 * C8 * CC * 4>>>(x, Wq, Wk);
    attn_kernel<<<NWIN, 256>>>();
    gemm_t_kernel<<<dim3(16, NWIN), 256>>>(x);
    gemm_o_kernel<<<dim3(16, NWIN), 256>>>(x, Wv, gam);
    ffn_mma_kernel<<<BQ * HH, 256, FFN_SMEM_BYTES>>>(W1, b1, W2, b2, ln1w, ln1b, ln2w, ln2b, out);
}

// round 4
// speedup vs baseline: 3.3942x; 1.4289x over previous
#include <cuda_runtime.h>
#include <cuda_bf16.h>
#include <math.h>
#include <stdint.h>

#define BQ   8
#define CC   256
#define HH   128
#define WWD  128
#define GG   16
#define NWIN 512
#define NT   256
#define C8   32
#define FF   1024
#define HW   16384

// ---------------- device scratch ----------------
__device__ __align__(128) float g_q[(size_t)NWIN * NT * C8];
__device__ __align__(128) float g_k[(size_t)NWIN * NT * C8];
__device__ __align__(128) float g_xa[(size_t)BQ * CC * HH * WWD];

// ================= helpers =================
__device__ __forceinline__ uint32_t smem_u32(const void* p) {
    uint32_t a;
    asm("{ .reg .u64 t; cvta.to.shared.u64 t, %1; cvt.u32.u64 %0, t; }" : "=r"(a) : "l"(p));
    return a;
}
__device__ __forceinline__ float tf32r(float v) {
    uint32_t r; asm("cvt.rna.tf32.f32 %0, %1;" : "=r"(r) : "f"(v));
    return __uint_as_float(r);
}
__device__ __forceinline__ void mma_tf32(float* d, uint32_t a0, uint32_t a1, uint32_t a2, uint32_t a3,
                                         uint32_t b0, uint32_t b1) {
    asm volatile(
        "mma.sync.aligned.m16n8k8.row.col.f32.tf32.tf32.f32 "
        "{%0,%1,%2,%3}, {%4,%5,%6,%7}, {%8,%9}, {%0,%1,%2,%3};"
        : "+f"(d[0]), "+f"(d[1]), "+f"(d[2]), "+f"(d[3])
        : "r"(a0), "r"(a1), "r"(a2), "r"(a3), "r"(b0), "r"(b1));
}
__device__ __forceinline__ void mma_bf16(float* d, uint32_t a0, uint32_t a1, uint32_t a2, uint32_t a3,
                                         uint32_t b0, uint32_t b1) {
    asm volatile(
        "mma.sync.aligned.m16n8k16.row.col.f32.bf16.bf16.f32 "
        "{%0,%1,%2,%3}, {%4,%5,%6,%7}, {%8,%9}, {%0,%1,%2,%3};"
        : "+f"(d[0]), "+f"(d[1]), "+f"(d[2]), "+f"(d[3])
        : "r"(a0), "r"(a1), "r"(a2), "r"(a3), "r"(b0), "r"(b1));
}
__device__ __forceinline__ uint32_t packbf(float a, float b) {
    __nv_bfloat162 h = __float22bfloat162_rn(make_float2(a, b));
    return *(uint32_t*)&h;
}
#define CP16(dst, src) asm volatile("cp.async.cg.shared.global [%0], [%1], 16;" :: "r"(dst), "l"(src))
#define CP_COMMIT()    asm volatile("cp.async.commit_group;" ::: "memory")
#define CP_WAIT1()     asm volatile("cp.async.wait_group 1;" ::: "memory")

__device__ __forceinline__ float gelu_exact(float v) { return v * normcdff(v); }

// ------------------------------------------------------------------
// Kernel 1: q/k projections per window (fp32 SIMT)
// ------------------------------------------------------------------
__global__ void __launch_bounds__(256) qk_kernel(const float* __restrict__ x,
                                                 const float* __restrict__ Wq,
                                                 const float* __restrict__ Wk)
{
    extern __shared__ float s[];
    float* sq = s;
    float* sk = s + C8 * CC;
    int tid = threadIdx.x;
    for (int i = tid; i < C8 * CC; i += 256) { sq[i] = Wq[i]; sk[i] = Wk[i]; }
    __syncthreads();

    int w = blockIdx.x;
    int b = w >> 6, r = w & 63, ih = r >> 3, iw = r & 7;
    int n = tid, gy = n >> 4, gx = n & 15;
    const float* xp = x + (size_t)b * CC * HW + (ih * GG + gy) * WWD + iw * GG + gx;

    float qa[C8], ka[C8];
#pragma unroll
    for (int o = 0; o < C8; o++) { qa[o] = 0.f; ka[o] = 0.f; }

    for (int c = 0; c < CC; c += 4) {
        float v0 = xp[(size_t)(c + 0) * HW];
        float v1 = xp[(size_t)(c + 1) * HW];
        float v2 = xp[(size_t)(c + 2) * HW];
        float v3 = xp[(size_t)(c + 3) * HW];
#pragma unroll
        for (int o = 0; o < C8; o++) {
            float4 a = *(const float4*)&sq[o * CC + c];
            qa[o] = fmaf(a.x, v0, fmaf(a.y, v1, fmaf(a.z, v2, fmaf(a.w, v3, qa[o]))));
            float4 bb = *(const float4*)&sk[o * CC + c];
            ka[o] = fmaf(bb.x, v0, fmaf(bb.y, v1, fmaf(bb.z, v2, fmaf(bb.w, v3, ka[o]))));
        }
    }
    float* qdst = g_q + (size_t)w * NT * C8 + n * C8;
    float* kdst = g_k + (size_t)w * NT * C8 + n * C8;
#pragma unroll
    for (int o = 0; o < C8; o += 4) {
        *(float4*)&qdst[o] = make_float4(qa[o], qa[o + 1], qa[o + 2], qa[o + 3]);
        *(float4*)&kdst[o] = make_float4(ka[o], ka[o + 1], ka[o + 2], ka[o + 3]);
    }
}

// ------------------------------------------------------------------
// Kernel 2: FUSED attention core (bf16 mma.sync), one CTA per window.
// S = q k^T -> softmax (fp32) -> t = E @ xw^T -> out = t @ Wv^T
// epilogue: g_xa = gamma*out/z + x
// smem (bytes):
//   XS2 @ 0       : xw bf16 [256c][264]           135168
//   ES  @ 135168  : E bf16 [64m][264] (alias TS)   33792
//   QS  @ 168960  : q bf16 [256tok][36]            18432
//   KS  @ 187392  : k bf16 [256tok][36]            18432
//   RED @ 205824  : 4x64 fp32 reductions            1024
//   ZS  @ 206848  : 64 fp32 gamma/z                  256
// total 207104 -> alloc 207872
// ------------------------------------------------------------------
#define AT_XS2 0
#define AT_ES  135168
#define AT_TS  135168
#define AT_QS  168960
#define AT_KS  187392
#define AT_RED 205824
#define AT_ZS  206848
#define AT_SMEM 207872

__global__ void __launch_bounds__(256) attn_fused_kernel(const float* __restrict__ x,
                                                         const float* __restrict__ Wv,
                                                         const float* __restrict__ gamma)
{
    extern __shared__ __align__(16) char sp[];
    const int tid = threadIdx.x, lane = tid & 31, wp = tid >> 5;
    const int g = lane >> 2, t = lane & 3;
    const int w = blockIdx.x, b = w >> 6, ih = (w >> 3) & 7, iw = w & 7;

    const float* xw = x + (size_t)b * CC * HW + ih * GG * WWD + iw * GG;
    const float gam = __ldg(gamma);

    // ---- stage xw -> XS2 bf16 [c][n] ----
    for (int it = 0; it < 128; it++) {
        int i = it * 256 + tid;
        int c = i >> 7, pr = i & 127;
        int n = pr * 2, gy = n >> 4, gx = n & 15;
        float2 v = *(const float2*)(xw + (size_t)c * HW + gy * WWD + gx);
        *(uint32_t*)(sp + AT_XS2 + c * 528 + n * 2) = packbf(v.x, v.y);
    }
    // ---- stage q,k -> QS/KS bf16 [tok][o] ----
    {
        const float* qsrc = g_q + (size_t)w * NT * C8;
        const float* ksrc = g_k + (size_t)w * NT * C8;
        for (int it = 0; it < 16; it++) {
            int i = it * 256 + tid;
            int tok = i >> 4, op = (i & 15) * 2;
            float2 q2 = *(const float2*)(qsrc + tok * 32 + op);
            *(uint32_t*)(sp + AT_QS + tok * 72 + op * 2) = packbf(q2.x, q2.y);
            float2 k2 = *(const float2*)(ksrc + tok * 32 + op);
            *(uint32_t*)(sp + AT_KS + tok * 72 + op * 2) = packbf(k2.x, k2.y);
        }
    }
    __syncthreads();

    const int wm = wp >> 2, wn = wp & 3;
    const int m0s = wm * 32, n0s = wn * 64;
    const int c0 = wp * 32;
    float* red = (float*)(sp + AT_RED);
    float* zs = (float*)(sp + AT_ZS);

    for (int mq = 0; mq < 4; mq++) {
        const int mqb = mq * 64;

        // ================= S-GEMM: S[64m][256n], warp = 32m x 64n =================
        float S[2][8][4];
#pragma unroll
        for (int mi = 0; mi < 2; mi++)
#pragma unroll
            for (int ni = 0; ni < 8; ni++)
#pragma unroll
                for (int r = 0; r < 4; r++) S[mi][ni][r] = 0.f;

#pragma unroll
        for (int ks = 0; ks < 2; ks++) {
            uint32_t A[2][4];
#pragma unroll
            for (int mi = 0; mi < 2; mi++) {
                const char* ab = sp + AT_QS + (mqb + m0s + mi * 16 + g) * 72 + ks * 32 + t * 4;
                A[mi][0] = *(const uint32_t*)ab;
                A[mi][1] = *(const uint32_t*)(ab + 8 * 72);
                A[mi][2] = *(const uint32_t*)(ab + 16);
                A[mi][3] = *(const uint32_t*)(ab + 8 * 72 + 16);
            }
#pragma unroll
            for (int ni = 0; ni < 8; ni++) {
                const char* bb = sp + AT_KS + (n0s + ni * 8 + g) * 72 + ks * 32 + t * 4;
                uint32_t b0 = *(const uint32_t*)bb;
                uint32_t b1 = *(const uint32_t*)(bb + 16);
                mma_bf16(S[0][ni], A[0][0], A[0][1], A[0][2], A[0][3], b0, b1);
                mma_bf16(S[1][ni], A[1][0], A[1][1], A[1][2], A[1][3], b0, b1);
            }
        }

        // ================= softmax (fp32) =================
        float mx[2][2];
#pragma unroll
        for (int mi = 0; mi < 2; mi++) {
            mx[mi][0] = -1e30f; mx[mi][1] = -1e30f;
#pragma unroll
            for (int ni = 0; ni < 8; ni++) {
                mx[mi][0] = fmaxf(mx[mi][0], fmaxf(S[mi][ni][0], S[mi][ni][1]));
                mx[mi][1] = fmaxf(mx[mi][1], fmaxf(S[mi][ni][2], S[mi][ni][3]));
            }
#pragma unroll
            for (int h = 0; h < 2; h++) {
                mx[mi][h] = fmaxf(mx[mi][h], __shfl_xor_sync(0xffffffff, mx[mi][h], 1));
                mx[mi][h] = fmaxf(mx[mi][h], __shfl_xor_sync(0xffffffff, mx[mi][h], 2));
            }
        }
        if (t == 0) {
#pragma unroll
            for (int mi = 0; mi < 2; mi++)
#pragma unroll
                for (int h = 0; h < 2; h++)
                    red[wn * 64 + m0s + mi * 16 + g + 8 * h] = mx[mi][h];
        }
        __syncthreads();
        float gmx[2][2], sum[2][2];
#pragma unroll
        for (int mi = 0; mi < 2; mi++)
#pragma unroll
            for (int h = 0; h < 2; h++) {
                int row = m0s + mi * 16 + g + 8 * h;
                gmx[mi][h] = fmaxf(fmaxf(red[row], red[64 + row]),
                                   fmaxf(red[128 + row], red[192 + row]));
                sum[mi][h] = 0.f;
            }
        // exp + write E (unnormalized) + partial sums
#pragma unroll
        for (int mi = 0; mi < 2; mi++) {
#pragma unroll
            for (int ni = 0; ni < 8; ni++) {
                float e0 = __expf(S[mi][ni][0] - gmx[mi][0]);
                float e1 = __expf(S[mi][ni][1] - gmx[mi][0]);
                float e2 = __expf(S[mi][ni][2] - gmx[mi][1]);
                float e3 = __expf(S[mi][ni][3] - gmx[mi][1]);
                sum[mi][0] += e0 + e1;
                sum[mi][1] += e2 + e3;
                int ncol = (n0s + ni * 8 + 2 * t) * 2;
                *(uint32_t*)(sp + AT_ES + (m0s + mi * 16 + g) * 528 + ncol) = packbf(e0, e1);
                *(uint32_t*)(sp + AT_ES + (m0s + mi * 16 + g + 8) * 528 + ncol) = packbf(e2, e3);
            }
#pragma unroll
            for (int h = 0; h < 2; h++) {
                sum[mi][h] += __shfl_xor_sync(0xffffffff, sum[mi][h], 1);
                sum[mi][h] += __shfl_xor_sync(0xffffffff, sum[mi][h], 2);
            }
        }
        __syncthreads();
        if (t == 0) {
#pragma unroll
            for (int mi = 0; mi < 2; mi++)
#pragma unroll
                for (int h = 0; h < 2; h++)
                    red[wn * 64 + m0s + mi * 16 + g + 8 * h] = sum[mi][h];
        }
        __syncthreads();
        if (wn == 0 && t == 0) {
#pragma unroll
            for (int mi = 0; mi < 2; mi++)
#pragma unroll
                for (int h = 0; h < 2; h++) {
                    int row = m0s + mi * 16 + g + 8 * h;
                    float z = red[row] + red[64 + row] + red[128 + row] + red[192 + row];
                    zs[row] = gam / z;
                }
        }
        __syncthreads();

        // ================= t-GEMM: Dt[64m][256c], warp = 64m x 32c =================
        float Dt[4][4][4];
#pragma unroll
        for (int mi = 0; mi < 4; mi++)
#pragma unroll
            for (int ci = 0; ci < 4; ci++)
#pragma unroll
                for (int r = 0; r < 4; r++) Dt[mi][ci][r] = 0.f;

#pragma unroll 4
        for (int kk = 0; kk < 16; kk++) {
            uint32_t A[4][4];
#pragma unroll
            for (int mi = 0; mi < 4; mi++) {
                const char* ab = sp + AT_ES + (mi * 16 + g) * 528 + kk * 32 + t * 4;
                A[mi][0] = *(const uint32_t*)ab;
                A[mi][1] = *(const uint32_t*)(ab + 8 * 528);
                A[mi][2] = *(const uint32_t*)(ab + 16);
                A[mi][3] = *(const uint32_t*)(ab + 8 * 528 + 16);
            }
#pragma unroll
            for (int ci = 0; ci < 4; ci++) {
                const char* bb = sp + AT_XS2 + (c0 + ci * 8 + g) * 528 + kk * 32 + t * 4;
                uint32_t b0 = *(const uint32_t*)bb;
                uint32_t b1 = *(const uint32_t*)(bb + 16);
#pragma unroll
                for (int mi = 0; mi < 4; mi++)
                    mma_bf16(Dt[mi][ci], A[mi][0], A[mi][1], A[mi][2], A[mi][3], b0, b1);
            }
        }
        __syncthreads();
        // write ts[m][c] (aliases ES)
#pragma unroll
        for (int mi = 0; mi < 4; mi++)
#pragma unroll
            for (int ci = 0; ci < 4; ci++) {
                int ccol = (c0 + ci * 8 + 2 * t) * 2;
                *(uint32_t*)(sp + AT_TS + (mi * 16 + g) * 528 + ccol) = packbf(Dt[mi][ci][0], Dt[mi][ci][1]);
                *(uint32_t*)(sp + AT_TS + (mi * 16 + g + 8) * 528 + ccol) = packbf(Dt[mi][ci][2], Dt[mi][ci][3]);
            }
        __syncthreads();

        // ================= out-GEMM: Do[64m][256co], warp = 64m x 32co =================
        float Do[4][4][4];
#pragma unroll
        for (int mi = 0; mi < 4; mi++)
#pragma unroll
            for (int cj = 0; cj < 4; cj++)
#pragma unroll
                for (int r = 0; r < 4; r++) Do[mi][cj][r] = 0.f;

#pragma unroll 4
        for (int kk = 0; kk < 16; kk++) {
            uint32_t A[4][4];
#pragma unroll
            for (int mi = 0; mi < 4; mi++) {
                const char* ab = sp + AT_TS + (mi * 16 + g) * 528 + kk * 32 + t * 4;
                A[mi][0] = *(const uint32_t*)ab;
                A[mi][1] = *(const uint32_t*)(ab + 8 * 528);
                A[mi][2] = *(const uint32_t*)(ab + 16);
                A[mi][3] = *(const uint32_t*)(ab + 8 * 528 + 16);
            }
#pragma unroll
            for (int cj = 0; cj < 4; cj++) {
                const float* wv = Wv + (size_t)(c0 + cj * 8 + g) * CC + kk * 16 + 2 * t;
                float2 f0 = *(const float2*)wv;
                float2 f1 = *(const float2*)(wv + 8);
                uint32_t b0 = packbf(f0.x, f0.y);
                uint32_t b1 = packbf(f1.x, f1.y);
#pragma unroll
                for (int mi = 0; mi < 4; mi++)
                    mma_bf16(Do[mi][cj], A[mi][0], A[mi][1], A[mi][2], A[mi][3], b0, b1);
            }
        }

        // ================= epilogue: gamma*out/z + x -> g_xa =================
        {
            float* xab = g_xa + (size_t)b * CC * HW + ih * GG * WWD + iw * GG;
#pragma unroll
            for (int mi = 0; mi < 4; mi++) {
                int m_lo = mi * 16 + g, m_hi = m_lo + 8;
                float z0 = zs[m_lo], z1 = zs[m_hi];
                int tok0 = mqb + m_lo, tok1 = mqb + m_hi;
                int p0 = (tok0 >> 4) * WWD + (tok0 & 15);
                int p1 = (tok1 >> 4) * WWD + (tok1 & 15);
#pragma unroll
                for (int cj = 0; cj < 4; cj++) {
                    int co = c0 + cj * 8 + 2 * t;
                    size_t o00 = (size_t)co * HW + p0;
                    size_t o01 = (size_t)(co + 1) * HW + p0;
                    size_t o10 = (size_t)co * HW + p1;
                    size_t o11 = (size_t)(co + 1) * HW + p1;
                    xab[o00] = Do[mi][cj][0] * z0 + xw[o00];
                    xab[o01] = Do[mi][cj][1] * z0 + xw[o01];
                    xab[o10] = Do[mi][cj][2] * z1 + xw[o10];
                    xab[o11] = Do[mi][cj][3] * z1 + xw[o11];
                }
            }
        }
    }
}

// ------------------------------------------------------------------
// Kernel 3: mma.sync tf32 FFN + LN1/LN2 + residuals (unchanged)
// ------------------------------------------------------------------
#define XS_OFF 0
#define HS_OFF 33792
#define W1_OFF 38016
#define W2_OFF 46336
#define FFN_SMEM_FLOATS 55552
#define FFN_SMEM_BYTES (FFN_SMEM_FLOATS * 4)

__global__ void __launch_bounds__(256) ffn_mma_kernel(const float* __restrict__ W1,
                                                      const float* __restrict__ b1,
                                                      const float* __restrict__ W2,
                                                      const float* __restrict__ b2,
                                                      const float* __restrict__ ln1w,
                                                      const float* __restrict__ ln1b,
                                                      const float* __restrict__ ln2w,
                                                      const float* __restrict__ ln2b,
                                                      float* __restrict__ out)
{
    extern __shared__ __align__(16) float sm[];
    float* xs  = sm + XS_OFF;
    float* hs  = sm + HS_OFF;
    float* w1s = sm + W1_OFF;
    float* w2s = sm + W2_OFF;
    const uint32_t w1u = smem_u32(w1s);
    const uint32_t w2u = smem_u32(w2s);

    const int tid = threadIdx.x, lane = tid & 31, wp = tid >> 5;
    const int g = lane >> 2, t = lane & 3;
    const int blk = blockIdx.x, b = blk >> 7, row = blk & 127;

    const int fr0 = (wp >> 2) * 16;
    const int px0 = (wp & 3) * 32;
    const int pxm0 = (wp & 3) * 32;
    const int c0w = (wp >> 2) * 128;

    {
        for (int j = 0; j < 8; j++) {
            int id = tid + j * 256;
            int f = id >> 6, seg = id & 63;
            CP16(w1u + (uint32_t)(f * 260 + seg * 4) * 4u,
                 W1 + (size_t)f * CC + seg * 4);
        }
        CP_COMMIT();
        for (int j = 0; j < 8; j++) {
            int id = tid + j * 256;
            int c = id >> 3, seg = id & 7;
            CP16(w2u + (uint32_t)(c * 36 + seg * 4) * 4u,
                 W2 + (size_t)c * FF + seg * 4);
        }
        CP_COMMIT();
    }

    {
        const float* xab = g_xa + (size_t)b * CC * HW + (size_t)row * WWD;
        int px = tid & 127, ch = tid >> 7;
#pragma unroll 8
        for (int it = 0; it < 128; it++) {
            int c = ch + it * 2;
            xs[c * 132 + px] = tf32r(xab[(size_t)c * HW + px]);
        }
    }

    float yacc[2][16][4];
#pragma unroll
    for (int mf = 0; mf < 2; mf++)
#pragma unroll
        for (int nf = 0; nf < 16; nf++)
#pragma unroll
            for (int r = 0; r < 4; r++) yacc[mf][nf][r] = 0.f;

    for (int ft = 0; ft < 32; ft++) {
        const int ftb = ft * 32;
        CP_WAIT1();
        __syncthreads();

        float d1[4][4];
#pragma unroll
        for (int nf = 0; nf < 4; nf++)
#pragma unroll
            for (int r = 0; r < 4; r++) d1[nf][r] = 0.f;

        {
            const float* wr0 = w1s + (fr0 + g) * 260;
            const float* wr1 = wr0 + 8 * 260;
            const float* xb0 = xs + t * 132 + px0 + g;
#pragma unroll
            for (int ks = 0; ks < 32; ks++) {
                int k = ks * 8;
                uint32_t a0 = __float_as_uint(wr0[k + t]);
                uint32_t a1 = __float_as_uint(wr1[k + t]);
                uint32_t a2 = __float_as_uint(wr0[k + t + 4]);
                uint32_t a3 = __float_as_uint(wr1[k + t + 4]);
                const float* xk = xb0 + k * 132;
#pragma unroll
                for (int nf = 0; nf < 4; nf++) {
                    uint32_t b0 = __float_as_uint(xk[nf * 8]);
                    uint32_t b1 = __float_as_uint(xk[4 * 132 + nf * 8]);
                    mma_tf32(d1[nf], a0, a1, a2, a3, b0, b1);
                }
            }
        }
        __syncthreads();
        if (ft < 31) {
            const float* src = W1 + (size_t)(ftb + 32) * CC;
            for (int j = 0; j < 8; j++) {
                int id = tid + j * 256;
                int f = id >> 6, seg = id & 63;
                CP16(w1u + (uint32_t)(f * 260 + seg * 4) * 4u,
                     src + (size_t)f * CC + seg * 4);
            }
        }
        CP_COMMIT();

        {
            float b1a = __ldg(&b1[ftb + fr0 + g]);
            float b1b = __ldg(&b1[ftb + fr0 + g + 8]);
#pragma unroll
            for (int nf = 0; nf < 4; nf++) {
                int px = px0 + nf * 8 + 2 * t;
                float2 v01 = make_float2(tf32r(gelu_exact(d1[nf][0] + b1a)),
                                         tf32r(gelu_exact(d1[nf][1] + b1a)));
                float2 v23 = make_float2(tf32r(gelu_exact(d1[nf][2] + b1b)),
                                         tf32r(gelu_exact(d1[nf][3] + b1b)));
                *(float2*)&hs[(fr0 + g) * 132 + px] = v01;
                *(float2*)&hs[(fr0 + g + 8) * 132 + px] = v23;
            }
        }
        CP_WAIT1();
        __syncthreads();

        {
#pragma unroll
            for (int ks = 0; ks < 4; ks++) {
                int k = ks * 8;
                uint32_t am[2][4];
#pragma unroll
                for (int mf = 0; mf < 2; mf++) {
                    const float* hb = hs + (k + t) * 132 + pxm0 + 16 * mf + g;
                    am[mf][0] = __float_as_uint(hb[0]);
                    am[mf][1] = __float_as_uint(hb[8]);
                    am[mf][2] = __float_as_uint(hb[4 * 132]);
                    am[mf][3] = __float_as_uint(hb[4 * 132 + 8]);
                }
#pragma unroll
                for (int nf = 0; nf < 16; nf++) {
                    const float* wb = w2s + (c0w + nf * 8 + g) * 36 + k + t;
                    uint32_t b0 = __float_as_uint(wb[0]);
                    uint32_t b1 = __float_as_uint(wb[4]);
                    mma_tf32(yacc[0][nf], am[0][0], am[0][1], am[0][2], am[0][3], b0, b1);
                    mma_tf32(yacc[1][nf], am[1][0], am[1][1], am[1][2], am[1][3], b0, b1);
                }
            }
        }
        __syncthreads();
        if (ft < 31) {
            const float* src = W2 + (size_t)(ftb + 32);
            for (int j = 0; j < 8; j++) {
                int id = tid + j * 256;
                int c = id >> 3, seg = id & 7;
                CP16(w2u + (uint32_t)(c * 36 + seg * 4) * 4u,
                     src + (size_t)c * FF + seg * 4);
            }
        }
        CP_COMMIT();
    }
    __syncthreads();

    float* ys = sm;
#pragma unroll
    for (int nf = 0; nf < 16; nf++) {
        int c = c0w + nf * 8 + 2 * t;
        float b2a = __ldg(&b2[c]);
        float b2b = __ldg(&b2[c + 1]);
#pragma unroll
        for (int mf = 0; mf < 2; mf++) {
            int pxr = pxm0 + 16 * mf + g;
            *(float2*)&ys[pxr * 260 + c] =
                make_float2(yacc[mf][nf][0] + b2a, yacc[mf][nf][1] + b2b);
            *(float2*)&ys[(pxr + 8) * 260 + c] =
                make_float2(yacc[mf][nf][2] + b2a, yacc[mf][nf][3] + b2b);
        }
    }
    __syncthreads();

    int px = tid >> 1, hf = tid & 1;
    float* yrow = ys + px * 260 + hf * 128;
    float* red = hs;

    float s1 = 0.f, s2 = 0.f;
#pragma unroll 8
    for (int i = 0; i < 128; i += 4) {
        float4 v = *(float4*)&yrow[i];
        s1 += v.x + v.y + v.z + v.w;
        s2 += v.x * v.x + v.y * v.y + v.z * v.z + v.w * v.w;
    }
    red[tid] = s1; red[512 + tid] = s2;
    __syncthreads();
    float mu = (red[px * 2] + red[px * 2 + 1]) * (1.f / 256.f);
    float va = (red[512 + px * 2] + red[512 + px * 2 + 1]) * (1.f / 256.f);
    float rstd = rsqrtf(va - mu * mu + 1e-5f);

    const float* xsrc = g_xa + ((size_t)(b * CC) + hf * 128) * HW + (size_t)row * WWD + px;
    float t1 = 0.f, t2 = 0.f;
    for (int i = 0; i < 128; i++) {
        int c = hf * 128 + i;
        float x2v = xsrc[(size_t)i * HW] + (yrow[i] - mu) * rstd * ln1w[c] + ln1b[c];
        yrow[i] = x2v;
        t1 += x2v; t2 += x2v * x2v;
    }
    __syncthreads();
    red[tid] = t1; red[512 + tid] = t2;
    __syncthreads();
    float mu2 = (red[px * 2] + red[px * 2 + 1]) * (1.f / 256.f);
    float va2 = (red[512 + px * 2] + red[512 + px * 2 + 1]) * (1.f / 256.f);
    float rstd2 = rsqrtf(va2 - mu2 * mu2 + 1e-5f);

    float* op = out + ((size_t)(b * CC) + hf * 128) * HW + (size_t)row * WWD + px;
    for (int i = 0; i < 128; i++) {
        int c = hf * 128 + i;
        float v = yrow[i];
        op[(size_t)i * HW] = v + (v - mu2) * rstd2 * ln2w[c] + ln2b[c];
    }
}

// ------------------------------------------------------------------
extern "C" void kernel_launch(void* const* d_in, const int* in_sizes, int n_in,
                              void* d_out, int out_size)
{
    const float* x    = (const float*)d_in[0];
    const float* Wq   = (const float*)d_in[1];
    const float* Wk   = (const float*)d_in[2];
    const float* Wv   = (const float*)d_in[3];
    const float* gam  = (const float*)d_in[4];
    const float* W1   = (const float*)d_in[5];
    const float* b1   = (const float*)d_in[6];
    const float* W2   = (const float*)d_in[7];
    const float* b2   = (const float*)d_in[8];
    const float* ln1w = (const float*)d_in[9];
    const float* ln1b = (const float*)d_in[10];
    const float* ln2w = (const float*)d_in[11];
    const float* ln2b = (const float*)d_in[12];
    float* out = (float*)d_out;

    cudaFuncSetAttribute(qk_kernel, cudaFuncAttributeMaxDynamicSharedMemorySize, 2 * C8 * CC * 4);
    cudaFuncSetAttribute(attn_fused_kernel, cudaFuncAttributeMaxDynamicSharedMemorySize, AT_SMEM);
    cudaFuncSetAttribute(ffn_mma_kernel, cudaFuncAttributeMaxDynamicSharedMemorySize, FFN_SMEM_BYTES);

    qk_kernel<<<NWIN, 256, 2 * C8 * CC * 4>>>(x, Wq, Wk);
    attn_fused_kernel<<<NWIN, 256, AT_SMEM>>>(x, Wv, gam);
    ffn_mma_kernel<<<BQ * HH, 256, FFN_SMEM_BYTES>>>(W1, b1, W2, b2, ln1w, ln1b, ln2w, ln2b, out);
}

// round 6
// speedup vs baseline: 3.7223x; 1.0967x over previous
#include <cuda_runtime.h>
#include <cuda_bf16.h>
#include <math.h>
#include <stdint.h>

#define BQ   8
#define CC   256
#define HH   128
#define WWD  128
#define GG   16
#define NWIN 512
#define NT   256
#define C8   32
#define FF   1024
#define HW   16384

// ---------------- device scratch ----------------
__device__ __align__(128) float g_xa[(size_t)BQ * CC * HH * WWD];

// ================= helpers =================
__device__ __forceinline__ uint32_t smem_u32(const void* p) {
    uint32_t a;
    asm("{ .reg .u64 t; cvta.to.shared.u64 t, %1; cvt.u32.u64 %0, t; }" : "=r"(a) : "l"(p));
    return a;
}
__device__ __forceinline__ float tf32r(float v) {
    uint32_t r; asm("cvt.rna.tf32.f32 %0, %1;" : "=r"(r) : "f"(v));
    return __uint_as_float(r);
}
__device__ __forceinline__ void mma_tf32(float* d, uint32_t a0, uint32_t a1, uint32_t a2, uint32_t a3,
                                         uint32_t b0, uint32_t b1) {
    asm volatile(
        "mma.sync.aligned.m16n8k8.row.col.f32.tf32.tf32.f32 "
        "{%0,%1,%2,%3}, {%4,%5,%6,%7}, {%8,%9}, {%0,%1,%2,%3};"
        : "+f"(d[0]), "+f"(d[1]), "+f"(d[2]), "+f"(d[3])
        : "r"(a0), "r"(a1), "r"(a2), "r"(a3), "r"(b0), "r"(b1));
}
__device__ __forceinline__ void mma_bf16(float* d, uint32_t a0, uint32_t a1, uint32_t a2, uint32_t a3,
                                         uint32_t b0, uint32_t b1) {
    asm volatile(
        "mma.sync.aligned.m16n8k16.row.col.f32.bf16.bf16.f32 "
        "{%0,%1,%2,%3}, {%4,%5,%6,%7}, {%8,%9}, {%0,%1,%2,%3};"
        : "+f"(d[0]), "+f"(d[1]), "+f"(d[2]), "+f"(d[3])
        : "r"(a0), "r"(a1), "r"(a2), "r"(a3), "r"(b0), "r"(b1));
}
__device__ __forceinline__ uint32_t packbf(float a, float b) {
    __nv_bfloat162 h = __float22bfloat162_rn(make_float2(a, b));
    return *(uint32_t*)&h;
}
#define CP16(dst, src) asm volatile("cp.async.cg.shared.global [%0], [%1], 16;" :: "r"(dst), "l"(src))
#define CP_COMMIT()    asm volatile("cp.async.commit_group;" ::: "memory")
#define CP_WAIT1()     asm volatile("cp.async.wait_group 1;" ::: "memory")

__device__ __forceinline__ float gelu_exact(float v) { return v * normcdff(v); }

// ------------------------------------------------------------------
// Kernel 1: FUSED window attention, one CTA per window.
// q,k = Wq,Wk @ xw (bf16 MMA, fused) -> S = q^T k -> softmax(fp32) ->
// t = E @ xw^T -> out = t @ Wv^T -> g_xa = gamma*out/z + x
// smem (bytes):
//   XS  @ 0       : xw bf16 [256c][264tok]         135168
//   ES  @ 135168  : E/ts bf16 [64][264] (alias WQS/WKS) 33792
//   QS  @ 168960  : q bf16 [256tok][36o]            18432
//   KS  @ 187392  : k bf16 [256tok][36o]            18432
//   RED @ 205824  : 4x64 fp32                        1024
//   ZS  @ 206848  : 64 fp32                           256
// ------------------------------------------------------------------
#define AT_XS  0
#define AT_ES  135168
#define AT_TS  135168
#define AT_WQS 135168
#define AT_WKS (135168 + 16896)
#define AT_QS  168960
#define AT_KS  187392
#define AT_RED 205824
#define AT_ZS  206848
#define AT_SMEM 207104

__global__ void __launch_bounds__(256) attn_fused_kernel(const float* __restrict__ x,
                                                         const float* __restrict__ Wq,
                                                         const float* __restrict__ Wk,
                                                         const float* __restrict__ Wv,
                                                         const float* __restrict__ gamma)
{
    extern __shared__ __align__(16) char sp[];
    const int tid = threadIdx.x, lane = tid & 31, wp = tid >> 5;
    const int g = lane >> 2, t = lane & 3;
    const int w = blockIdx.x, b = w >> 6, ih = (w >> 3) & 7, iw = w & 7;

    const float* xw = x + (size_t)b * CC * HW + ih * GG * WWD + iw * GG;
    const float gam = __ldg(gamma);

    // ---- stage xw -> XS bf16 [c][264tok] ----
    for (int it = 0; it < 128; it++) {
        int i = it * 256 + tid;
        int c = i >> 7, pr = i & 127;
        int n = pr * 2, gy = n >> 4, gx = n & 15;
        float2 v = *(const float2*)(xw + (size_t)c * HW + gy * WWD + gx);
        *(uint32_t*)(sp + AT_XS + c * 528 + n * 2) = packbf(v.x, v.y);
    }
    // ---- stage Wq/Wk -> WQS/WKS bf16 [32o][264c] (ES alias) ----
    for (int it = 0; it < 16; it++) {
        int i = it * 256 + tid;
        int o = i >> 7, cp2 = (i & 127) * 2;
        float2 q2 = *(const float2*)(Wq + (size_t)o * CC + cp2);
        *(uint32_t*)(sp + AT_WQS + o * 528 + cp2 * 2) = packbf(q2.x, q2.y);
        float2 k2 = *(const float2*)(Wk + (size_t)o * CC + cp2);
        *(uint32_t*)(sp + AT_WKS + o * 528 + cp2 * 2) = packbf(k2.x, k2.y);
    }
    __syncthreads();

    // ================= qk-GEMM: D[32o][256tok]; warp owns 32 tokens =================
    {
        const int n0 = wp * 32;
        const uint16_t* xb16 = (const uint16_t*)(sp + AT_XS);
        float Dq[2][4][4], Dk[2][4][4];
#pragma unroll
        for (int mi = 0; mi < 2; mi++)
#pragma unroll
            for (int nf = 0; nf < 4; nf++)
#pragma unroll
                for (int r = 0; r < 4; r++) { Dq[mi][nf][r] = 0.f; Dk[mi][nf][r] = 0.f; }

#pragma unroll 4
        for (int ks = 0; ks < 16; ks++) {
            uint32_t Aq[2][4], Ak[2][4];
#pragma unroll
            for (int mi = 0; mi < 2; mi++) {
                const char* aq = sp + AT_WQS + (mi * 16 + g) * 528 + ks * 32 + t * 4;
                Aq[mi][0] = *(const uint32_t*)aq;
                Aq[mi][1] = *(const uint32_t*)(aq + 8 * 528);
                Aq[mi][2] = *(const uint32_t*)(aq + 16);
                Aq[mi][3] = *(const uint32_t*)(aq + 8 * 528 + 16);
                const char* ak = sp + AT_WKS + (mi * 16 + g) * 528 + ks * 32 + t * 4;
                Ak[mi][0] = *(const uint32_t*)ak;
                Ak[mi][1] = *(const uint32_t*)(ak + 8 * 528);
                Ak[mi][2] = *(const uint32_t*)(ak + 16);
                Ak[mi][3] = *(const uint32_t*)(ak + 8 * 528 + 16);
            }
            int c0k = ks * 16 + 2 * t;
#pragma unroll
            for (int nf = 0; nf < 4; nf++) {
                int tok = n0 + nf * 8 + g;
                uint32_t b0 = (uint32_t)xb16[c0k * 264 + tok]
                            | ((uint32_t)xb16[(c0k + 1) * 264 + tok] << 16);
                uint32_t b1 = (uint32_t)xb16[(c0k + 8) * 264 + tok]
                            | ((uint32_t)xb16[(c0k + 9) * 264 + tok] << 16);
#pragma unroll
                for (int mi = 0; mi < 2; mi++) {
                    mma_bf16(Dq[mi][nf], Aq[mi][0], Aq[mi][1], Aq[mi][2], Aq[mi][3], b0, b1);
                    mma_bf16(Dk[mi][nf], Ak[mi][0], Ak[mi][1], Ak[mi][2], Ak[mi][3], b0, b1);
                }
            }
        }
        __nv_bfloat16* qs = (__nv_bfloat16*)(sp + AT_QS);
        __nv_bfloat16* ksm = (__nv_bfloat16*)(sp + AT_KS);
#pragma unroll
        for (int mi = 0; mi < 2; mi++)
#pragma unroll
            for (int nf = 0; nf < 4; nf++) {
                int o_lo = mi * 16 + g, o_hi = o_lo + 8;
                int tok = n0 + nf * 8 + 2 * t;
                qs[tok * 36 + o_lo] = __float2bfloat16(Dq[mi][nf][0]);
                qs[(tok + 1) * 36 + o_lo] = __float2bfloat16(Dq[mi][nf][1]);
                qs[tok * 36 + o_hi] = __float2bfloat16(Dq[mi][nf][2]);
                qs[(tok + 1) * 36 + o_hi] = __float2bfloat16(Dq[mi][nf][3]);
                ksm[tok * 36 + o_lo] = __float2bfloat16(Dk[mi][nf][0]);
                ksm[(tok + 1) * 36 + o_lo] = __float2bfloat16(Dk[mi][nf][1]);
                ksm[tok * 36 + o_hi] = __float2bfloat16(Dk[mi][nf][2]);
                ksm[(tok + 1) * 36 + o_hi] = __float2bfloat16(Dk[mi][nf][3]);
            }
    }
    __syncthreads();

    const int wm = wp >> 2, wn = wp & 3;
    const int m0s = wm * 32, n0s = wn * 64;
    const int c0 = wp * 32;
    float* red = (float*)(sp + AT_RED);
    float* zs = (float*)(sp + AT_ZS);

    for (int mq = 0; mq < 4; mq++) {
        const int mqb = mq * 64;

        // ================= S-GEMM: S[64m][256n], warp = 32m x 64n =================
        float S[2][8][4];
#pragma unroll
        for (int mi = 0; mi < 2; mi++)
#pragma unroll
            for (int ni = 0; ni < 8; ni++)
#pragma unroll
                for (int r = 0; r < 4; r++) S[mi][ni][r] = 0.f;

#pragma unroll
        for (int ks = 0; ks < 2; ks++) {
            uint32_t A[2][4];
#pragma unroll
            for (int mi = 0; mi < 2; mi++) {
                const char* ab = sp + AT_QS + (mqb + m0s + mi * 16 + g) * 72 + ks * 32 + t * 4;
                A[mi][0] = *(const uint32_t*)ab;
                A[mi][1] = *(const uint32_t*)(ab + 8 * 72);
                A[mi][2] = *(const uint32_t*)(ab + 16);
                A[mi][3] = *(const uint32_t*)(ab + 8 * 72 + 16);
            }
#pragma unroll
            for (int ni = 0; ni < 8; ni++) {
                const char* bb = sp + AT_KS + (n0s + ni * 8 + g) * 72 + ks * 32 + t * 4;
                uint32_t b0 = *(const uint32_t*)bb;
                uint32_t b1 = *(const uint32_t*)(bb + 16);
                mma_bf16(S[0][ni], A[0][0], A[0][1], A[0][2], A[0][3], b0, b1);
                mma_bf16(S[1][ni], A[1][0], A[1][1], A[1][2], A[1][3], b0, b1);
            }
        }

        // ================= softmax (fp32) =================
        float mx[2][2];
#pragma unroll
        for (int mi = 0; mi < 2; mi++) {
            mx[mi][0] = -1e30f; mx[mi][1] = -1e30f;
#pragma unroll
            for (int ni = 0; ni < 8; ni++) {
                mx[mi][0] = fmaxf(mx[mi][0], fmaxf(S[mi][ni][0], S[mi][ni][1]));
                mx[mi][1] = fmaxf(mx[mi][1], fmaxf(S[mi][ni][2], S[mi][ni][3]));
            }
#pragma unroll
            for (int h = 0; h < 2; h++) {
                mx[mi][h] = fmaxf(mx[mi][h], __shfl_xor_sync(0xffffffff, mx[mi][h], 1));
                mx[mi][h] = fmaxf(mx[mi][h], __shfl_xor_sync(0xffffffff, mx[mi][h], 2));
            }
        }
        if (t == 0) {
#pragma unroll
            for (int mi = 0; mi < 2; mi++)
#pragma unroll
                for (int h = 0; h < 2; h++)
                    red[wn * 64 + m0s + mi * 16 + g + 8 * h] = mx[mi][h];
        }
        __syncthreads();
        float gmx[2][2], sum[2][2];
#pragma unroll
        for (int mi = 0; mi < 2; mi++)
#pragma unroll
            for (int h = 0; h < 2; h++) {
                int row = m0s + mi * 16 + g + 8 * h;
                gmx[mi][h] = fmaxf(fmaxf(red[row], red[64 + row]),
                                   fmaxf(red[128 + row], red[192 + row]));
                sum[mi][h] = 0.f;
            }
#pragma unroll
        for (int mi = 0; mi < 2; mi++) {
#pragma unroll
            for (int ni = 0; ni < 8; ni++) {
                float e0 = __expf(S[mi][ni][0] - gmx[mi][0]);
                float e1 = __expf(S[mi][ni][1] - gmx[mi][0]);
                float e2 = __expf(S[mi][ni][2] - gmx[mi][1]);
                float e3 = __expf(S[mi][ni][3] - gmx[mi][1]);
                sum[mi][0] += e0 + e1;
                sum[mi][1] += e2 + e3;
                int ncol = (n0s + ni * 8 + 2 * t) * 2;
                *(uint32_t*)(sp + AT_ES + (m0s + mi * 16 + g) * 528 + ncol) = packbf(e0, e1);
                *(uint32_t*)(sp + AT_ES + (m0s + mi * 16 + g + 8) * 528 + ncol) = packbf(e2, e3);
            }
#pragma unroll
            for (int h = 0; h < 2; h++) {
                sum[mi][h] += __shfl_xor_sync(0xffffffff, sum[mi][h], 1);
                sum[mi][h] += __shfl_xor_sync(0xffffffff, sum[mi][h], 2);
            }
        }
        __syncthreads();
        if (t == 0) {
#pragma unroll
            for (int mi = 0; mi < 2; mi++)
#pragma unroll
                for (int h = 0; h < 2; h++)
                    red[wn * 64 + m0s + mi * 16 + g + 8 * h] = sum[mi][h];
        }
        __syncthreads();
        if (wn == 0 && t == 0) {
#pragma unroll
            for (int mi = 0; mi < 2; mi++)
#pragma unroll
                for (int h = 0; h < 2; h++) {
                    int row = m0s + mi * 16 + g + 8 * h;
                    float z = red[row] + red[64 + row] + red[128 + row] + red[192 + row];
                    zs[row] = gam / z;
                }
        }
        __syncthreads();

        // ================= t-GEMM: Dt[64m][256c], warp = 64m x 32c =================
        float Dt[4][4][4];
#pragma unroll
        for (int mi = 0; mi < 4; mi++)
#pragma unroll
            for (int ci = 0; ci < 4; ci++)
#pragma unroll
                for (int r = 0; r < 4; r++) Dt[mi][ci][r] = 0.f;

#pragma unroll 4
        for (int kk = 0; kk < 16; kk++) {
            uint32_t A[4][4];
#pragma unroll
            for (int mi = 0; mi < 4; mi++) {
                const char* ab = sp + AT_ES + (mi * 16 + g) * 528 + kk * 32 + t * 4;
                A[mi][0] = *(const uint32_t*)ab;
                A[mi][1] = *(const uint32_t*)(ab + 8 * 528);
                A[mi][2] = *(const uint32_t*)(ab + 16);
                A[mi][3] = *(const uint32_t*)(ab + 8 * 528 + 16);
            }
#pragma unroll
            for (int ci = 0; ci < 4; ci++) {
                const char* bb = sp + AT_XS + (c0 + ci * 8 + g) * 528 + kk * 32 + t * 4;
                uint32_t b0 = *(const uint32_t*)bb;
                uint32_t b1 = *(const uint32_t*)(bb + 16);
#pragma unroll
                for (int mi = 0; mi < 4; mi++)
                    mma_bf16(Dt[mi][ci], A[mi][0], A[mi][1], A[mi][2], A[mi][3], b0, b1);
            }
        }
        __syncthreads();
#pragma unroll
        for (int mi = 0; mi < 4; mi++)
#pragma unroll
            for (int ci = 0; ci < 4; ci++) {
                int ccol = (c0 + ci * 8 + 2 * t) * 2;
                *(uint32_t*)(sp + AT_TS + (mi * 16 + g) * 528 + ccol) = packbf(Dt[mi][ci][0], Dt[mi][ci][1]);
                *(uint32_t*)(sp + AT_TS + (mi * 16 + g + 8) * 528 + ccol) = packbf(Dt[mi][ci][2], Dt[mi][ci][3]);
            }
        __syncthreads();

        // ================= out-GEMM: Do[64m][256co], warp = 64m x 32co =================
        float Do[4][4][4];
#pragma unroll
        for (int mi = 0; mi < 4; mi++)
#pragma unroll
            for (int cj = 0; cj < 4; cj++)
#pragma unroll
                for (int r = 0; r < 4; r++) Do[mi][cj][r] = 0.f;

#pragma unroll 4
        for (int kk = 0; kk < 16; kk++) {
            uint32_t A[4][4];
#pragma unroll
            for (int mi = 0; mi < 4; mi++) {
                const char* ab = sp + AT_TS + (mi * 16 + g) * 528 + kk * 32 + t * 4;
                A[mi][0] = *(const uint32_t*)ab;
                A[mi][1] = *(const uint32_t*)(ab + 8 * 528);
                A[mi][2] = *(const uint32_t*)(ab + 16);
                A[mi][3] = *(const uint32_t*)(ab + 8 * 528 + 16);
            }
#pragma unroll
            for (int cj = 0; cj < 4; cj++) {
                const float* wv = Wv + (size_t)(c0 + cj * 8 + g) * CC + kk * 16 + 2 * t;
                float2 f0 = *(const float2*)wv;
                float2 f1 = *(const float2*)(wv + 8);
                uint32_t b0 = packbf(f0.x, f0.y);
                uint32_t b1 = packbf(f1.x, f1.y);
#pragma unroll
                for (int mi = 0; mi < 4; mi++)
                    mma_bf16(Do[mi][cj], A[mi][0], A[mi][1], A[mi][2], A[mi][3], b0, b1);
            }
        }

        // ================= epilogue: gamma*out/z + x -> g_xa =================
        {
            float* xab = g_xa + (size_t)b * CC * HW + ih * GG * WWD + iw * GG;
#pragma unroll
            for (int mi = 0; mi < 4; mi++) {
                int m_lo = mi * 16 + g, m_hi = m_lo + 8;
                float z0 = zs[m_lo], z1 = zs[m_hi];
                int tok0 = mqb + m_lo, tok1 = mqb + m_hi;
                int p0 = (tok0 >> 4) * WWD + (tok0 & 15);
                int p1 = (tok1 >> 4) * WWD + (tok1 & 15);
#pragma unroll
                for (int cj = 0; cj < 4; cj++) {
                    int co = c0 + cj * 8 + 2 * t;
                    size_t o00 = (size_t)co * HW + p0;
                    size_t o01 = (size_t)(co + 1) * HW + p0;
                    size_t o10 = (size_t)co * HW + p1;
                    size_t o11 = (size_t)(co + 1) * HW + p1;
                    xab[o00] = Do[mi][cj][0] * z0 + xw[o00];
                    xab[o01] = Do[mi][cj][1] * z0 + xw[o01];
                    xab[o10] = Do[mi][cj][2] * z1 + xw[o10];
                    xab[o11] = Do[mi][cj][3] * z1 + xw[o11];
                }
            }
        }
    }
}

// ------------------------------------------------------------------
// Kernel 2: mma.sync tf32 FFN + LN1/LN2 + residuals (unchanged)
// ------------------------------------------------------------------
#define XS_OFF 0
#define HS_OFF 33792
#define W1_OFF 38016
#define W2_OFF 46336
#define FFN_SMEM_FLOATS 55552
#define FFN_SMEM_BYTES (FFN_SMEM_FLOATS * 4)

__global__ void __launch_bounds__(256) ffn_mma_kernel(const float* __restrict__ W1,
                                                      const float* __restrict__ b1,
                                                      const float* __restrict__ W2,
                                                      const float* __restrict__ b2,
                                                      const float* __restrict__ ln1w,
                                                      const float* __restrict__ ln1b,
                                                      const float* __restrict__ ln2w,
                                                      const float* __restrict__ ln2b,
                                                      float* __restrict__ out)
{
    extern __shared__ __align__(16) float sm[];
    float* xs  = sm + XS_OFF;
    float* hs  = sm + HS_OFF;
    float* w1s = sm + W1_OFF;
    float* w2s = sm + W2_OFF;
    const uint32_t w1u = smem_u32(w1s);
    const uint32_t w2u = smem_u32(w2s);

    const int tid = threadIdx.x, lane = tid & 31, wp = tid >> 5;
    const int g = lane >> 2, t = lane & 3;
    const int blk = blockIdx.x, b = blk >> 7, row = blk & 127;

    const int fr0 = (wp >> 2) * 16;
    const int px0 = (wp & 3) * 32;
    const int pxm0 = (wp & 3) * 32;
    const int c0w = (wp >> 2) * 128;

    {
        for (int j = 0; j < 8; j++) {
            int id = tid + j * 256;
            int f = id >> 6, seg = id & 63;
            CP16(w1u + (uint32_t)(f * 260 + seg * 4) * 4u,
                 W1 + (size_t)f * CC + seg * 4);
        }
        CP_COMMIT();
        for (int j = 0; j < 8; j++) {
            int id = tid + j * 256;
            int c = id >> 3, seg = id & 7;
            CP16(w2u + (uint32_t)(c * 36 + seg * 4) * 4u,
                 W2 + (size_t)c * FF + seg * 4);
        }
        CP_COMMIT();
    }

    {
        const float* xab = g_xa + (size_t)b * CC * HW + (size_t)row * WWD;
        int px = tid & 127, ch = tid >> 7;
#pragma unroll 8
        for (int it = 0; it < 128; it++) {
            int c = ch + it * 2;
            xs[c * 132 + px] = tf32r(xab[(size_t)c * HW + px]);
        }
    }

    float yacc[2][16][4];
#pragma unroll
    for (int mf = 0; mf < 2; mf++)
#pragma unroll
        for (int nf = 0; nf < 16; nf++)
#pragma unroll
            for (int r = 0; r < 4; r++) yacc[mf][nf][r] = 0.f;

    for (int ft = 0; ft < 32; ft++) {
        const int ftb = ft * 32;
        CP_WAIT1();
        __syncthreads();

        float d1[4][4];
#pragma unroll
        for (int nf = 0; nf < 4; nf++)
#pragma unroll
            for (int r = 0; r < 4; r++) d1[nf][r] = 0.f;

        {
            const float* wr0 = w1s + (fr0 + g) * 260;
            const float* wr1 = wr0 + 8 * 260;
            const float* xb0 = xs + t * 132 + px0 + g;
#pragma unroll
            for (int ks = 0; ks < 32; ks++) {
                int k = ks * 8;
                uint32_t a0 = __float_as_uint(wr0[k + t]);
                uint32_t a1 = __float_as_uint(wr1[k + t]);
                uint32_t a2 = __float_as_uint(wr0[k + t + 4]);
                uint32_t a3 = __float_as_uint(wr1[k + t + 4]);
                const float* xk = xb0 + k * 132;
#pragma unroll
                for (int nf = 0; nf < 4; nf++) {
                    uint32_t b0 = __float_as_uint(xk[nf * 8]);
                    uint32_t b1 = __float_as_uint(xk[4 * 132 + nf * 8]);
                    mma_tf32(d1[nf], a0, a1, a2, a3, b0, b1);
                }
            }
        }
        __syncthreads();
        if (ft < 31) {
            const float* src = W1 + (size_t)(ftb + 32) * CC;
            for (int j = 0; j < 8; j++) {
                int id = tid + j * 256;
                int f = id >> 6, seg = id & 63;
                CP16(w1u + (uint32_t)(f * 260 + seg * 4) * 4u,
                     src + (size_t)f * CC + seg * 4);
            }
        }
        CP_COMMIT();

        {
            float b1a = __ldg(&b1[ftb + fr0 + g]);
            float b1b = __ldg(&b1[ftb + fr0 + g + 8]);
#pragma unroll
            for (int nf = 0; nf < 4; nf++) {
                int px = px0 + nf * 8 + 2 * t;
                float2 v01 = make_float2(tf32r(gelu_exact(d1[nf][0] + b1a)),
                                         tf32r(gelu_exact(d1[nf][1] + b1a)));
                float2 v23 = make_float2(tf32r(gelu_exact(d1[nf][2] + b1b)),
                                         tf32r(gelu_exact(d1[nf][3] + b1b)));
                *(float2*)&hs[(fr0 + g) * 132 + px] = v01;
                *(float2*)&hs[(fr0 + g + 8) * 132 + px] = v23;
            }
        }
        CP_WAIT1();
        __syncthreads();

        {
#pragma unroll
            for (int ks = 0; ks < 4; ks++) {
                int k = ks * 8;
                uint32_t am[2][4];
#pragma unroll
                for (int mf = 0; mf < 2; mf++) {
                    const float* hb = hs + (k + t) * 132 + pxm0 + 16 * mf + g;
                    am[mf][0] = __float_as_uint(hb[0]);
                    am[mf][1] = __float_as_uint(hb[8]);
                    am[mf][2] = __float_as_uint(hb[4 * 132]);
                    am[mf][3] = __float_as_uint(hb[4 * 132 + 8]);
                }
#pragma unroll
                for (int nf = 0; nf < 16; nf++) {
                    const float* wb = w2s + (c0w + nf * 8 + g) * 36 + k + t;
                    uint32_t b0 = __float_as_uint(wb[0]);
                    uint32_t b1 = __float_as_uint(wb[4]);
                    mma_tf32(yacc[0][nf], am[0][0], am[0][1], am[0][2], am[0][3], b0, b1);
                    mma_tf32(yacc[1][nf], am[1][0], am[1][1], am[1][2], am[1][3], b0, b1);
                }
            }
        }
        __syncthreads();
        if (ft < 31) {
            const float* src = W2 + (size_t)(ftb + 32);
            for (int j = 0; j < 8; j++) {
                int id = tid + j * 256;
                int c = id >> 3, seg = id & 7;
                CP16(w2u + (uint32_t)(c * 36 + seg * 4) * 4u,
                     src + (size_t)c * FF + seg * 4);
            }
        }
        CP_COMMIT();
    }
    __syncthreads();

    float* ys = sm;
#pragma unroll
    for (int nf = 0; nf < 16; nf++) {
        int c = c0w + nf * 8 + 2 * t;
        float b2a = __ldg(&b2[c]);
        float b2b = __ldg(&b2[c + 1]);
#pragma unroll
        for (int mf = 0; mf < 2; mf++) {
            int pxr = pxm0 + 16 * mf + g;
            *(float2*)&ys[pxr * 260 + c] =
                make_float2(yacc[mf][nf][0] + b2a, yacc[mf][nf][1] + b2b);
            *(float2*)&ys[(pxr + 8) * 260 + c] =
                make_float2(yacc[mf][nf][2] + b2a, yacc[mf][nf][3] + b2b);
        }
    }
    __syncthreads();

    int px = tid >> 1, hf = tid & 1;
    float* yrow = ys + px * 260 + hf * 128;
    float* red = hs;

    float s1 = 0.f, s2 = 0.f;
#pragma unroll 8
    for (int i = 0; i < 128; i += 4) {
        float4 v = *(float4*)&yrow[i];
        s1 += v.x + v.y + v.z + v.w;
        s2 += v.x * v.x + v.y * v.y + v.z * v.z + v.w * v.w;
    }
    red[tid] = s1; red[512 + tid] = s2;
    __syncthreads();
    float mu = (red[px * 2] + red[px * 2 + 1]) * (1.f / 256.f);
    float va = (red[512 + px * 2] + red[512 + px * 2 + 1]) * (1.f / 256.f);
    float rstd = rsqrtf(va - mu * mu + 1e-5f);

    const float* xsrc = g_xa + ((size_t)(b * CC) + hf * 128) * HW + (size_t)row * WWD + px;
    float t1 = 0.f, t2 = 0.f;
    for (int i = 0; i < 128; i++) {
        int c = hf * 128 + i;
        float x2v = xsrc[(size_t)i * HW] + (yrow[i] - mu) * rstd * ln1w[c] + ln1b[c];
        yrow[i] = x2v;
        t1 += x2v; t2 += x2v * x2v;
    }
    __syncthreads();
    red[tid] = t1; red[512 + tid] = t2;
    __syncthreads();
    float mu2 = (red[px * 2] + red[px * 2 + 1]) * (1.f / 256.f);
    float va2 = (red[512 + px * 2] + red[512 + px * 2 + 1]) * (1.f / 256.f);
    float rstd2 = rsqrtf(va2 - mu2 * mu2 + 1e-5f);

    float* op = out + ((size_t)(b * CC) + hf * 128) * HW + (size_t)row * WWD + px;
    for (int i = 0; i < 128; i++) {
        int c = hf * 128 + i;
        float v = yrow[i];
        op[(size_t)i * HW] = v + (v - mu2) * rstd2 * ln2w[c] + ln2b[c];
    }
}

// ------------------------------------------------------------------
extern "C" void kernel_launch(void* const* d_in, const int* in_sizes, int n_in,
                              void* d_out, int out_size)
{
    const float* x    = (const float*)d_in[0];
    const float* Wq   = (const float*)d_in[1];
    const float* Wk   = (const float*)d_in[2];
    const float* Wv   = (const float*)d_in[3];
    const float* gam  = (const float*)d_in[4];
    const float* W1   = (const float*)d_in[5];
    const float* b1   = (const float*)d_in[6];
    const float* W2   = (const float*)d_in[7];
    const float* b2   = (const float*)d_in[8];
    const float* ln1w = (const float*)d_in[9];
    const float* ln1b = (const float*)d_in[10];
    const float* ln2w = (const float*)d_in[11];
    const float* ln2b = (const float*)d_in[12];
    float* out = (float*)d_out;

    cudaFuncSetAttribute(attn_fused_kernel, cudaFuncAttributeMaxDynamicSharedMemorySize, AT_SMEM);
    cudaFuncSetAttribute(ffn_mma_kernel, cudaFuncAttributeMaxDynamicSharedMemorySize, FFN_SMEM_BYTES);

    attn_fused_kernel<<<NWIN, 256, AT_SMEM>>>(x, Wq, Wk, Wv, gam);
    ffn_mma_kernel<<<BQ * HH, 256, FFN_SMEM_BYTES>>>(W1, b1, W2, b2, ln1w, ln1b, ln2w, ln2b, out);
}